// round 5
// baseline (speedup 1.0000x reference)
#include <cuda_runtime.h>
#include <cuda_bf16.h>
#include <math.h>
#include <stdint.h>

#define NB    16
#define CIN   256
#define HW    1024
#define INNER 512
#define CTXN  77
#define CTXD  768
#define DH    64

// ===================== PTX helpers (sm_80-safe only) =========================
__device__ __forceinline__ uint32_t smem_to_u32(const void* p) {
    uint32_t a;
    asm("{ .reg .u64 t; cvta.to.shared.u64 t, %1; cvt.u32.u64 %0, t; }" : "=r"(a) : "l"(p));
    return a;
}
__device__ __forceinline__ void cp16(uint32_t dst, const void* src, bool valid) {
    int sz = valid ? 16 : 0;
    asm volatile("cp.async.cg.shared.global [%0], [%1], 16, %2;"
                 :: "r"(dst), "l"(src), "r"(sz) : "memory");
}
#define CP_COMMIT() asm volatile("cp.async.commit_group;" ::: "memory")
template <int N>
__device__ __forceinline__ void cp_wait() {
    asm volatile("cp.async.wait_group %0;" :: "n"(N) : "memory");
}
__device__ __forceinline__ void ldsm_x4(uint32_t* r, uint32_t addr) {
    asm volatile("ldmatrix.sync.aligned.m8n8.x4.shared.b16 {%0,%1,%2,%3}, [%4];"
        : "=r"(r[0]), "=r"(r[1]), "=r"(r[2]), "=r"(r[3]) : "r"(addr));
}
__device__ __forceinline__ void mma_bf16(float* d, const uint32_t* a,
                                         uint32_t b0, uint32_t b1) {
    asm volatile(
        "mma.sync.aligned.m16n8k16.row.col.f32.bf16.bf16.f32 "
        "{%0,%1,%2,%3}, {%4,%5,%6,%7}, {%8,%9}, {%0,%1,%2,%3};"
        : "+f"(d[0]), "+f"(d[1]), "+f"(d[2]), "+f"(d[3])
        : "r"(a[0]), "r"(a[1]), "r"(a[2]), "r"(a[3]), "r"(b0), "r"(b1));
}
__device__ __forceinline__ void mma_tf32(float* d, const uint32_t* a, const uint32_t* b) {
    asm volatile(
        "mma.sync.aligned.m16n8k8.row.col.f32.tf32.tf32.f32 "
        "{%0,%1,%2,%3}, {%4,%5,%6,%7}, {%8,%9}, {%0,%1,%2,%3};"
        : "+f"(d[0]), "+f"(d[1]), "+f"(d[2]), "+f"(d[3])
        : "r"(a[0]), "r"(a[1]), "r"(a[2]), "r"(a[3]), "r"(b[0]), "r"(b[1]));
}
__device__ __forceinline__ uint32_t f2tf32(float v) {
    uint32_t r;
    asm("cvt.rna.tf32.f32 %0, %1;" : "=r"(r) : "f"(v));
    return r;
}

// ===================== scratch (device globals) ==============================
#define WB_TOTAL 3567616L
__device__ __align__(16) __nv_bfloat16 g_wb[WB_TOTAL];
__device__ __align__(16) float g_xnf[NB * HW * CIN];
__device__ __align__(16) float g_h0 [NB * HW * INNER];
__device__ __align__(16) float g_h1 [NB * HW * INNER];
__device__ __align__(16) float g_of [NB * HW * INNER];
__device__ __align__(16) float g_h2 [NB * HW * INNER];
__device__ __align__(16) float g_kvc[NB * CTXN * 1024];
__device__ float g_stats[NB * 32 * 2];
__device__ __align__(16) __nv_bfloat16 g_hnb [NB * HW * INNER];
__device__ __align__(16) __nv_bfloat16 g_qb  [NB * HW * INNER];
__device__ __align__(16) __nv_bfloat16 g_kb  [NB * HW * INNER];
__device__ __align__(16) __nv_bfloat16 g_vtb [NB * HW * INNER];
__device__ __align__(16) __nv_bfloat16 g_h1b [NB * HW * INNER];
__device__ __align__(16) __nv_bfloat16 g_attn[(long)NB * HW * HW];

// ===================== reductions ============================================
__device__ __forceinline__ float warpSum(float v) {
#pragma unroll
    for (int o = 16; o; o >>= 1) v += __shfl_xor_sync(0xffffffffu, v, o);
    return v;
}
__device__ float blockSum(float v) {
    __shared__ float sm[8];
    int t = threadIdx.x;
    v = warpSum(v);
    if ((t & 31) == 0) sm[t >> 5] = v;
    __syncthreads();
    if (t < 32) {
        float w = (t < 8) ? sm[t] : 0.f;
        w = warpSum(w);
        if (t == 0) sm[0] = w;
    }
    __syncthreads();
    float r = sm[0];
    __syncthreads();
    return r;
}
__device__ __forceinline__ float warpMax(float v) {
#pragma unroll
    for (int o = 16; o; o >>= 1) v = fmaxf(v, __shfl_xor_sync(0xffffffffu, v, o));
    return v;
}
__device__ float blockMax(float v) {
    __shared__ float sm[8];
    int t = threadIdx.x;
    v = warpMax(v);
    if ((t & 31) == 0) sm[t >> 5] = v;
    __syncthreads();
    if (t < 32) {
        float w = (t < 8) ? sm[t] : -3.0e38f;
        w = warpMax(w);
        if (t == 0) sm[0] = w;
    }
    __syncthreads();
    float r = sm[0];
    __syncthreads();
    return r;
}

// ===================== conversions ===========================================
struct CvtSrc { const float* p[11]; };
__global__ void cvt_k(CvtSrc a) {
    long i = (long)blockIdx.x * 256 + threadIdx.x;
    if (i >= WB_TOTAL) return;
    const long ends[11] = {131072, 393216, 655360, 917504, 1179648, 1441792,
                           1835008, 2228224, 2490368, 2621440, 3567616};
    int s = 0; long off = 0;
#pragma unroll
    for (int k = 0; k < 11; k++) {
        if (i >= ends[k]) { s = k + 1; off = ends[k]; }
    }
    g_wb[i] = __float2bfloat16(a.p[s][i - off]);
}

// ===================== GroupNorm 1 (fp32 out, [b,n,c]) =======================
__global__ void gn1_stats_k(const float* __restrict__ x) {
    int bg = blockIdx.x;
    const float* p = x + (long)bg * 8192;
    float s = 0.f, ss = 0.f;
    for (int i = threadIdx.x; i < 2048; i += 256) {
        float4 v = ((const float4*)p)[i];
        s += v.x + v.y + v.z + v.w;
        ss += v.x * v.x + v.y * v.y + v.z * v.z + v.w * v.w;
    }
    s = blockSum(s); ss = blockSum(ss);
    if (threadIdx.x == 0) {
        float mean = s * (1.f / 8192.f);
        float var  = ss * (1.f / 8192.f) - mean * mean;
        g_stats[bg * 2]     = mean;
        g_stats[bg * 2 + 1] = rsqrtf(var + 1e-5f);
    }
}
__global__ void gn1_apply_k(const float* __restrict__ x,
                            const float* __restrict__ gam,
                            const float* __restrict__ bet) {
    int idx = blockIdx.x * 256 + threadIdx.x;
    int c = idx & 255;
    int n = (idx >> 8) & 1023;
    int b = idx >> 18;
    float v = x[((long)(b * 256 + c)) * 1024 + n];
    int sg = (b << 5) | (c >> 3);
    float mean = g_stats[sg * 2], rstd = g_stats[sg * 2 + 1];
    g_xnf[idx] = (v - mean) * rstd * gam[c] + bet[c];
}

// ===================== GroupNorm 2 (h0 fp32 -> hnb bf16) =====================
__global__ void gn2_k(const float* __restrict__ gg, const float* __restrict__ gb) {
    int b = blockIdx.x >> 5, g = blockIdx.x & 31;
    const float4* p = (const float4*)(g_h0 + (long)b * HW * INNER + g * 16);
    float s = 0.f, ss = 0.f;
    for (int i = threadIdx.x; i < HW * 4; i += 256) {
        int n = i >> 2, j = i & 3;
        float4 v = p[n * 128 + j];
        s += v.x + v.y + v.z + v.w;
        ss += v.x * v.x + v.y * v.y + v.z * v.z + v.w * v.w;
    }
    s = blockSum(s); ss = blockSum(ss);
    float mean = s * (1.f / 16384.f);
    float rstd = rsqrtf(ss * (1.f / 16384.f) - mean * mean + 1e-5f);
    __nv_bfloat16* q = g_hnb + (long)b * HW * INNER + g * 16;
    for (int i = threadIdx.x; i < HW * 4; i += 256) {
        int n = i >> 2, j = i & 3;
        int c = g * 16 + j * 4;
        float4 v = p[n * 128 + j];
        __nv_bfloat162 o0 = __floats2bfloat162_rn(
            (v.x - mean) * rstd * gg[c] + gb[c],
            (v.y - mean) * rstd * gg[c + 1] + gb[c + 1]);
        __nv_bfloat162 o1 = __floats2bfloat162_rn(
            (v.z - mean) * rstd * gg[c + 2] + gb[c + 2],
            (v.w - mean) * rstd * gg[c + 3] + gb[c + 3]);
        *(uint2*)(q + n * INNER + j * 4) = make_uint2(
            *(uint32_t*)&o0, *(uint32_t*)&o1);
    }
}

// ===================== softmax over 1024 (bf16 in/out) =======================
__global__ void softmax_k() {
    __nv_bfloat162* row = (__nv_bfloat162*)(g_attn + (long)blockIdx.x * HW);
    int t = threadIdx.x;
    __nv_bfloat162 a = row[t * 2], b = row[t * 2 + 1];
    float2 fa = __bfloat1622float2(a), fb = __bfloat1622float2(b);
    float m = blockMax(fmaxf(fmaxf(fa.x, fa.y), fmaxf(fb.x, fb.y)));
    fa.x = __expf(fa.x - m); fa.y = __expf(fa.y - m);
    fb.x = __expf(fb.x - m); fb.y = __expf(fb.y - m);
    float inv = 1.f / blockSum(fa.x + fa.y + fb.x + fb.y);
    fa.x *= inv; fa.y *= inv; fb.x *= inv; fb.y *= inv;
    row[t * 2]     = __floats2bfloat162_rn(fa.x, fa.y);
    row[t * 2 + 1] = __floats2bfloat162_rn(fb.x, fb.y);
}

// ===================== fused cross-attention (fp32 out) ======================
__global__ void __launch_bounds__(256) ca_attn_k() {
    __shared__ float Ks[CTXN][DH];
    __shared__ float Vs[CTXN][DH];
    int b = blockIdx.x >> 3, h = blockIdx.x & 7;
    const float* kp = g_kvc + (long)b * CTXN * 1024 + h * DH;
    for (int i = threadIdx.x; i < CTXN * DH; i += 256) {
        int j = i >> 6, d = i & 63;
        Ks[j][d] = kp[j * 1024 + d];
        Vs[j][d] = kp[j * 1024 + 512 + d];
    }
    __syncthreads();
    const float scale = 0.125f;
    int i = blockIdx.y * 256 + threadIdx.x;
    const __nv_bfloat16* qp = g_qb + ((long)(b * HW + i)) * INNER + h * DH;
    float qv[DH];
#pragma unroll
    for (int d = 0; d < DH; d += 8) {
        uint4 u = *(const uint4*)(qp + d);
        const __nv_bfloat162* h2 = (const __nv_bfloat162*)&u;
#pragma unroll
        for (int e = 0; e < 4; e++) {
            float2 f = __bfloat1622float2(h2[e]);
            qv[d + 2 * e] = f.x; qv[d + 2 * e + 1] = f.y;
        }
    }
    float l = 0.f, acc[DH];
#pragma unroll
    for (int d = 0; d < DH; d++) acc[d] = 0.f;
    for (int j = 0; j < CTXN; j++) {
        float s = 0.f;
#pragma unroll
        for (int d = 0; d < DH; d++) s += qv[d] * Ks[j][d];
        float e = __expf(s * scale);
        l += e;
#pragma unroll
        for (int d = 0; d < DH; d++) acc[d] += e * Vs[j][d];
    }
    float inv = 1.f / l;
    float* op = g_of + ((long)(b * HW + i)) * INNER + h * DH;
#pragma unroll
    for (int d = 0; d < DH; d += 4)
        *(float4*)(op + d) = make_float4(acc[d] * inv, acc[d + 1] * inv,
                                         acc[d + 2] * inv, acc[d + 3] * inv);
}

// ===================== mma.sync GEMM, 64x64 warp tiles, 3-stage ==============
// C[bz] = alpha * A[bz] @ B[bz]^T (+ bias[n]) (+ rcoef * R)
// DT=0: bf16 operands (BK=64).  DT=1: fp32 operands via tf32 (BK=32).
// A: [M,K] row-major; B: [N,K] row-major. CTA 128x128, 4 warps (2x2 of 64x64).
// Stage = 32KB (A 16KB + B 16KB), rows are 128B, XOR-swizzled in 16B units.
// TOUT: store (and read R) at [bz*M*N + n*M + m].
#define STAGE_B 32768
#define GSMEM   (3 * STAGE_B)
// fp32 smem element index for (row r, col c): 32 floats per row, swizzled
#define AIDX(r, c) ((r) * 32 + ((((c) >> 2) ^ ((r) & 7)) << 2) + ((c) & 3))

template <int DT, bool TOUT>
__global__ void __launch_bounds__(128, 2) gemm_mma(
    const void* __restrict__ A_, long sA,
    const void* __restrict__ B_, long sB,
    float* __restrict__ Cf, __nv_bfloat16* __restrict__ Cb,
    const float* __restrict__ bias, const float* __restrict__ R,
    float rcoef, float alpha, int M, int N, int K) {
    constexpr int ESZ = DT ? 4 : 2;
    constexpr int BK  = DT ? 32 : 64;
    extern __shared__ __align__(128) char sm[];
    const uint32_t sb = smem_to_u32(sm);
    const int tid  = threadIdx.x;
    const int lane = tid & 31;
    const int wid  = tid >> 5;
    const int bz = blockIdx.z;
    const int bm = blockIdx.y * 128;
    const int bn = blockIdx.x * 128;
    const int wm = (wid >> 1) * 64;
    const int wn = (wid & 1) * 64;
    const char* Ab = (const char*)A_ + (long)bz * sA * ESZ;
    const char* Bb = (const char*)B_ + (long)bz * sB * ESZ;

    float acc[4][8][4];
#pragma unroll
    for (int i = 0; i < 4; i++)
#pragma unroll
        for (int j = 0; j < 8; j++)
#pragma unroll
            for (int e = 0; e < 4; e++) acc[i][j][e] = 0.f;

    // loader: one 128B row per thread for each of A and B
    const int lrow = tid;
    const bool aValid = (bm + lrow) < M;
    const long aOff = aValid ? ((long)(bm + lrow) * K) * ESZ : 0;
    const long bOff = ((long)(bn + lrow) * K) * ESZ;
    const int nIter = K / BK;

#define LOADC(i, s) do {                                                        \
    uint32_t dA = sb + (s) * STAGE_B + lrow * 128;                              \
    uint32_t dB = dA + 16384;                                                   \
    const char* gA = Ab + aOff + (long)(i) * 128;                               \
    const char* gB = Bb + bOff + (long)(i) * 128;                               \
    _Pragma("unroll")                                                           \
    for (int u = 0; u < 8; u++) {                                               \
        uint32_t so = (uint32_t)((u ^ (lrow & 7)) << 4);                        \
        cp16(dA + so, gA + u * 16, aValid);                                     \
        cp16(dB + so, gB + u * 16, true);                                       \
    }                                                                           \
} while (0)

    LOADC(0, 0); CP_COMMIT();
    if (1 < nIter) { LOADC(1, 1); }
    CP_COMMIT();

    const int arow  = lane & 15;
    const int ahalf = (lane >> 4) & 1;
    const int tr  = lane >> 2;
    const int tcq = lane & 3;

    for (int it = 0; it < nIter; it++) {
        const int s = it % 3;
        if (it + 1 < nIter) cp_wait<1>(); else cp_wait<0>();
        __syncthreads();
        if (it + 2 < nIter) { LOADC(it + 2, (it + 2) % 3); CP_COMMIT(); }

        if (DT == 0) {
            const uint32_t aT = sb + s * STAGE_B;
            const uint32_t bT = aT + 16384;
#pragma unroll
            for (int kk = 0; kk < 4; kk++) {
                const int u = kk * 2 + ahalf;
                uint32_t af[4][4], bf[4][4];
#pragma unroll
                for (int mi = 0; mi < 4; mi++) {
                    int r = wm + mi * 16 + arow;
                    ldsm_x4(af[mi], aT + r * 128 + ((u ^ (r & 7)) << 4));
                }
#pragma unroll
                for (int p = 0; p < 4; p++) {
                    int r = wn + p * 16 + arow;
                    ldsm_x4(bf[p], bT + r * 128 + ((u ^ (r & 7)) << 4));
                }
#pragma unroll
                for (int mi = 0; mi < 4; mi++)
#pragma unroll
                    for (int p = 0; p < 4; p++) {
                        mma_bf16(acc[mi][2 * p],     af[mi], bf[p][0], bf[p][2]);
                        mma_bf16(acc[mi][2 * p + 1], af[mi], bf[p][1], bf[p][3]);
                    }
            }
        } else {
            const float* Af = (const float*)(sm + s * STAGE_B);
            const float* Bf = (const float*)(sm + s * STAGE_B + 16384);
#pragma unroll
            for (int kk = 0; kk < 4; kk++) {
                const int c0 = kk * 8;
                uint32_t af[4][4], bf[8][2];
#pragma unroll
                for (int mi = 0; mi < 4; mi++) {
                    int r0 = wm + mi * 16 + tr;
                    af[mi][0] = f2tf32(Af[AIDX(r0,     c0 + tcq)]);
                    af[mi][1] = f2tf32(Af[AIDX(r0 + 8, c0 + tcq)]);
                    af[mi][2] = f2tf32(Af[AIDX(r0,     c0 + tcq + 4)]);
                    af[mi][3] = f2tf32(Af[AIDX(r0 + 8, c0 + tcq + 4)]);
                }
#pragma unroll
                for (int nj = 0; nj < 8; nj++) {
                    int rn = wn + nj * 8 + tr;
                    bf[nj][0] = f2tf32(Bf[AIDX(rn, c0 + tcq)]);
                    bf[nj][1] = f2tf32(Bf[AIDX(rn, c0 + tcq + 4)]);
                }
#pragma unroll
                for (int mi = 0; mi < 4; mi++)
#pragma unroll
                    for (int nj = 0; nj < 8; nj++)
                        mma_tf32(acc[mi][nj], af[mi], bf[nj]);
            }
        }
        __syncthreads();
    }

    // ------------------------------ epilogue ------------------------------
    const int tc = (lane & 3) * 2;
    const long bzMN = (long)bz * M * N;
#pragma unroll
    for (int mi = 0; mi < 4; mi++) {
#pragma unroll
        for (int r2 = 0; r2 < 2; r2++) {
            const int m = bm + wm + mi * 16 + tr + r2 * 8;
            if (m >= M) continue;
#pragma unroll
            for (int nj = 0; nj < 8; nj++) {
                const int n = bn + wn + nj * 8 + tc;
                float v0 = acc[mi][nj][r2 * 2 + 0] * alpha;
                float v1 = acc[mi][nj][r2 * 2 + 1] * alpha;
                if (bias) { v0 += bias[n]; v1 += bias[n + 1]; }
                if (TOUT) {
                    const long i0 = bzMN + (long)n * M + m;
                    const long i1 = bzMN + (long)(n + 1) * M + m;
                    if (R) { v0 += rcoef * R[i0]; v1 += rcoef * R[i1]; }
                    if (Cf) { Cf[i0] = v0; Cf[i1] = v1; }
                    if (Cb) { Cb[i0] = __float2bfloat16(v0); Cb[i1] = __float2bfloat16(v1); }
                } else {
                    const long i0 = bzMN + (long)m * N + n;
                    if (R) {
                        float2 rv = *(const float2*)(R + i0);
                        v0 += rcoef * rv.x; v1 += rcoef * rv.y;
                    }
                    if (Cf) *(float2*)(Cf + i0) = make_float2(v0, v1);
                    if (Cb) *(__nv_bfloat162*)(Cb + i0) = __floats2bfloat162_rn(v0, v1);
                }
            }
        }
    }
#undef LOADC
}

static void gemm(int dt, bool tout,
                 const void* A, long sA, const void* B, long sB,
                 float* Cf, __nv_bfloat16* Cb, const float* bias, const float* R,
                 float rcoef, float alpha, int M, int N, int K) {
    dim3 grid(N / 128, (M + 127) / 128, NB);
    if (dt == 0) {
        if (tout) {
            cudaFuncSetAttribute(gemm_mma<0, true>,  cudaFuncAttributeMaxDynamicSharedMemorySize, GSMEM);
            gemm_mma<0, true ><<<grid, 128, GSMEM>>>(A, sA, B, sB, Cf, Cb, bias, R, rcoef, alpha, M, N, K);
        } else {
            cudaFuncSetAttribute(gemm_mma<0, false>, cudaFuncAttributeMaxDynamicSharedMemorySize, GSMEM);
            gemm_mma<0, false><<<grid, 128, GSMEM>>>(A, sA, B, sB, Cf, Cb, bias, R, rcoef, alpha, M, N, K);
        }
    } else {
        if (tout) {
            cudaFuncSetAttribute(gemm_mma<1, true>,  cudaFuncAttributeMaxDynamicSharedMemorySize, GSMEM);
            gemm_mma<1, true ><<<grid, 128, GSMEM>>>(A, sA, B, sB, Cf, Cb, bias, R, rcoef, alpha, M, N, K);
        } else {
            cudaFuncSetAttribute(gemm_mma<1, false>, cudaFuncAttributeMaxDynamicSharedMemorySize, GSMEM);
            gemm_mma<1, false><<<grid, 128, GSMEM>>>(A, sA, B, sB, Cf, Cb, bias, R, rcoef, alpha, M, N, K);
        }
    }
}

// ===================== driver ================================================
extern "C" void kernel_launch(void* const* d_in, const int* in_sizes, int n_in,
                              void* d_out, int out_size) {
    const float* x      = (const float*)d_in[0];
    const float* ctx    = (const float*)d_in[1];
    const float* gn1_g  = (const float*)d_in[2];
    const float* gn1_b  = (const float*)d_in[3];
    const float* w_in   = (const float*)d_in[4];
    const float* b_in   = (const float*)d_in[5];
    const float* sa_wk  = (const float*)d_in[6];
    const float* sa_wq  = (const float*)d_in[7];
    const float* sa_wv  = (const float*)d_in[8];
    const float* sa_wp  = (const float*)d_in[9];
    const float* sa_gng = (const float*)d_in[10];
    const float* sa_gnb = (const float*)d_in[11];
    const float* ca_wq  = (const float*)d_in[12];
    const float* ca_wk  = (const float*)d_in[13];
    const float* ca_wv  = (const float*)d_in[14];
    const float* ca_wo  = (const float*)d_in[15];
    const float* ca_bo  = (const float*)d_in[16];
    const float* w_out  = (const float*)d_in[17];
    const float* b_out  = (const float*)d_in[18];
    float* out = (float*)d_out;

    float *xnf, *h0, *h1, *of, *h2, *kvc;
    __nv_bfloat16 *wb, *hnb, *qb, *kb, *vtb, *h1b, *attn;
    cudaGetSymbolAddress((void**)&xnf, g_xnf);
    cudaGetSymbolAddress((void**)&h0,  g_h0);
    cudaGetSymbolAddress((void**)&h1,  g_h1);
    cudaGetSymbolAddress((void**)&of,  g_of);
    cudaGetSymbolAddress((void**)&h2,  g_h2);
    cudaGetSymbolAddress((void**)&kvc, g_kvc);
    cudaGetSymbolAddress((void**)&wb,  g_wb);
    cudaGetSymbolAddress((void**)&hnb, g_hnb);
    cudaGetSymbolAddress((void**)&qb,  g_qb);
    cudaGetSymbolAddress((void**)&kb,  g_kb);
    cudaGetSymbolAddress((void**)&vtb, g_vtb);
    cudaGetSymbolAddress((void**)&h1b, g_h1b);
    cudaGetSymbolAddress((void**)&attn, g_attn);

    __nv_bfloat16* wb_saq = wb + 131072;
    __nv_bfloat16* wb_sak = wb + 393216;
    __nv_bfloat16* wb_sav = wb + 655360;
    __nv_bfloat16* wb_caq = wb + 1179648;
    __nv_bfloat16* wb_cakv= wb + 1441792;   // ca_wk then ca_wv: [1024, 768]
    __nv_bfloat16* ctx_b  = wb + 2621440;

    const float inv_sqrt_c = 0.044194173824159216f;   // 512^-0.5

    // 0. convert weights + ctx to bf16 (attention path uses them)
    CvtSrc cs;
    cs.p[0] = w_in;  cs.p[1] = sa_wq; cs.p[2] = sa_wk; cs.p[3] = sa_wv;
    cs.p[4] = sa_wp; cs.p[5] = ca_wq; cs.p[6] = ca_wk; cs.p[7] = ca_wv;
    cs.p[8] = ca_wo; cs.p[9] = w_out; cs.p[10] = ctx;
    cvt_k<<<(int)((WB_TOTAL + 255) / 256), 256>>>(cs);

    // 1. GN1(x) -> xnf fp32 [b,n,c]
    gn1_stats_k<<<NB * 32, 256>>>(x);
    gn1_apply_k<<<NB * HW * CIN / 256, 256>>>(x, gn1_g, gn1_b);
    // 2. conv_in (tf32): h0 = xn @ w_in^T + b_in
    gemm(1, false, xnf, (long)HW * CIN, w_in, 0, h0, nullptr, b_in,
         nullptr, 0.f, 1.f, HW, INNER, CIN);
    // 3. GN2(h0) -> hnb bf16
    gn2_k<<<NB * 32, 256>>>(sa_gng, sa_gnb);
    // 4. q/k/v (bf16); v stored transposed
    gemm(0, false, hnb, (long)HW * INNER, wb_saq, 0, nullptr, qb, nullptr, nullptr, 0.f, 1.f, HW, INNER, INNER);
    gemm(0, false, hnb, (long)HW * INNER, wb_sak, 0, nullptr, kb, nullptr, nullptr, 0.f, 1.f, HW, INNER, INNER);
    gemm(0, true,  hnb, (long)HW * INNER, wb_sav, 0, nullptr, vtb, nullptr, nullptr, 0.f, 1.f, HW, INNER, INNER);
    // 5. sim = q @ k^T * c^-0.5 -> attn bf16
    gemm(0, false, qb, (long)HW * INNER, kb, (long)HW * INNER, nullptr, attn,
         nullptr, nullptr, 0.f, inv_sqrt_c, HW, HW, INNER);
    // 6. softmax
    softmax_k<<<NB * HW, 256>>>();
    // 7. o = attn @ v (bf16 operands, fp32 out)
    gemm(0, false, attn, (long)HW * HW, vtb, (long)INNER * HW, of, nullptr,
         nullptr, nullptr, 0.f, 1.f, HW, INNER, HW);
    // 8. h1 = o @ wp^T + 2*h0 (tf32; fp32 + bf16 copies)
    gemm(1, false, of, (long)HW * INNER, sa_wp, 0, h1, h1b, nullptr,
         h0, 2.f, 1.f, HW, INNER, INNER);
    // 9. CA projections: q (bf16), fused k|v (bf16, fp32 out)
    gemm(0, false, h1b, (long)HW * INNER, wb_caq, 0, nullptr, qb, nullptr, nullptr, 0.f, 1.f, HW, INNER, INNER);
    gemm(0, false, ctx_b, (long)CTXN * CTXD, wb_cakv, 0, kvc, nullptr, nullptr, nullptr, 0.f, 1.f, CTXN, 1024, CTXD);
    // 10. fused cross-attention -> of fp32
    ca_attn_k<<<dim3(NB * 8, 4), 256>>>();
    // 11. h2 = o @ ca_wo^T + ca_bo + h1 (tf32, fp32 out)
    gemm(1, false, of, (long)HW * INNER, ca_wo, 0, h2, nullptr, ca_bo,
         h1, 1.f, 1.f, HW, INNER, INNER);
    // 12. out = h2 @ w_out^T + b_out + x (tf32, TOUT -> NCHW)
    gemm(1, true, h2, (long)HW * INNER, w_out, 0, out, nullptr, b_out,
         x, 1.f, 1.f, HW, CIN, INNER);
}

// round 6
// speedup vs baseline: 1.2035x; 1.2035x over previous
#include <cuda_runtime.h>
#include <cuda_bf16.h>
#include <math.h>
#include <stdint.h>

#define NB    16
#define CIN   256
#define HW    1024
#define INNER 512
#define CTXN  77
#define CTXD  768
#define DH    64

// ===================== PTX helpers (sm_80-safe only) =========================
__device__ __forceinline__ uint32_t smem_to_u32(const void* p) {
    uint32_t a;
    asm("{ .reg .u64 t; cvta.to.shared.u64 t, %1; cvt.u32.u64 %0, t; }" : "=r"(a) : "l"(p));
    return a;
}
__device__ __forceinline__ void cp16(uint32_t dst, const void* src, bool valid) {
    int sz = valid ? 16 : 0;
    asm volatile("cp.async.cg.shared.global [%0], [%1], 16, %2;"
                 :: "r"(dst), "l"(src), "r"(sz) : "memory");
}
#define CP_COMMIT() asm volatile("cp.async.commit_group;" ::: "memory")
template <int N>
__device__ __forceinline__ void cp_wait() {
    asm volatile("cp.async.wait_group %0;" :: "n"(N) : "memory");
}
__device__ __forceinline__ void ldsm_x4(uint32_t* r, uint32_t addr) {
    asm volatile("ldmatrix.sync.aligned.m8n8.x4.shared.b16 {%0,%1,%2,%3}, [%4];"
        : "=r"(r[0]), "=r"(r[1]), "=r"(r[2]), "=r"(r[3]) : "r"(addr));
}
__device__ __forceinline__ void mma_bf16(float* d, const uint32_t* a,
                                         uint32_t b0, uint32_t b1) {
    asm volatile(
        "mma.sync.aligned.m16n8k16.row.col.f32.bf16.bf16.f32 "
        "{%0,%1,%2,%3}, {%4,%5,%6,%7}, {%8,%9}, {%0,%1,%2,%3};"
        : "+f"(d[0]), "+f"(d[1]), "+f"(d[2]), "+f"(d[3])
        : "r"(a[0]), "r"(a[1]), "r"(a[2]), "r"(a[3]), "r"(b0), "r"(b1));
}
__device__ __forceinline__ void mma_tf32(float* d, const uint32_t* a,
                                         uint32_t b0, uint32_t b1) {
    asm volatile(
        "mma.sync.aligned.m16n8k8.row.col.f32.tf32.tf32.f32 "
        "{%0,%1,%2,%3}, {%4,%5,%6,%7}, {%8,%9}, {%0,%1,%2,%3};"
        : "+f"(d[0]), "+f"(d[1]), "+f"(d[2]), "+f"(d[3])
        : "r"(a[0]), "r"(a[1]), "r"(a[2]), "r"(a[3]), "r"(b0), "r"(b1));
}
__device__ __forceinline__ float tf32r(float v) {
    uint32_t r;
    asm("cvt.rna.tf32.f32 %0, %1;" : "=r"(r) : "f"(v));
    return __uint_as_float(r);
}

// ===================== scratch (device globals) ==============================
#define WB_TOTAL 3567616L
#define WTF_TOTAL 786432L
__device__ __align__(16) __nv_bfloat16 g_wb[WB_TOTAL];      // bf16 weights + ctx
__device__ __align__(16) float g_wtf[WTF_TOTAL];            // tf32 trunk weights
__device__ __align__(16) float g_xnf[NB * HW * CIN];        // GN1 out (tf32-rounded)
__device__ __align__(16) float g_h0 [NB * HW * INNER];      // conv_in out (full fp32)
__device__ __align__(16) float g_h1 [NB * HW * INNER];      // after SA (full fp32)
__device__ __align__(16) float g_of [NB * HW * INNER];      // attn outs (tf32-rounded)
__device__ __align__(16) float g_h2 [NB * HW * INNER];      // after CA (tf32-rounded)
__device__ __align__(16) float g_kvc[NB * CTXN * 1024];
__device__ float g_stats[NB * 32 * 2];
__device__ __align__(16) __nv_bfloat16 g_hnb [NB * HW * INNER];
__device__ __align__(16) __nv_bfloat16 g_qkb [NB * HW * 1024];  // q|k merged
__device__ __align__(16) __nv_bfloat16 g_qb  [NB * HW * INNER]; // CA q
__device__ __align__(16) __nv_bfloat16 g_vtb [NB * HW * INNER];
__device__ __align__(16) __nv_bfloat16 g_h1b [NB * HW * INNER];
__device__ __align__(16) __nv_bfloat16 g_attn[(long)NB * HW * HW];

// ===================== reductions ============================================
__device__ __forceinline__ float warpSum(float v) {
#pragma unroll
    for (int o = 16; o; o >>= 1) v += __shfl_xor_sync(0xffffffffu, v, o);
    return v;
}
__device__ float blockSum(float v) {
    __shared__ float sm[8];
    int t = threadIdx.x;
    v = warpSum(v);
    if ((t & 31) == 0) sm[t >> 5] = v;
    __syncthreads();
    if (t < 32) {
        float w = (t < 8) ? sm[t] : 0.f;
        w = warpSum(w);
        if (t == 0) sm[0] = w;
    }
    __syncthreads();
    float r = sm[0];
    __syncthreads();
    return r;
}
__device__ __forceinline__ float warpMax(float v) {
#pragma unroll
    for (int o = 16; o; o >>= 1) v = fmaxf(v, __shfl_xor_sync(0xffffffffu, v, o));
    return v;
}
__device__ float blockMax(float v) {
    __shared__ float sm[8];
    int t = threadIdx.x;
    v = warpMax(v);
    if ((t & 31) == 0) sm[t >> 5] = v;
    __syncthreads();
    if (t < 32) {
        float w = (t < 8) ? sm[t] : -3.0e38f;
        w = warpMax(w);
        if (t == 0) sm[0] = w;
    }
    __syncthreads();
    float r = sm[0];
    __syncthreads();
    return r;
}

// ===================== conversions ===========================================
struct CvtSrc { const float* p[11]; };
__global__ void cvt_k(CvtSrc a) {
    long i = (long)blockIdx.x * 256 + threadIdx.x;
    if (i >= WB_TOTAL) return;
    const long ends[11] = {131072, 393216, 655360, 917504, 1179648, 1441792,
                           1835008, 2228224, 2490368, 2621440, 3567616};
    int s = 0; long off = 0;
#pragma unroll
    for (int k = 0; k < 11; k++) {
        if (i >= ends[k]) { s = k + 1; off = ends[k]; }
    }
    g_wb[i] = __float2bfloat16(a.p[s][i - off]);
}
struct CvtTf { const float* p[4]; };
__global__ void cvt_tf_k(CvtTf a) {   // w_in | sa_wp | ca_wo | w_out (tf32-rounded)
    long i = (long)blockIdx.x * 256 + threadIdx.x;
    if (i >= WTF_TOTAL) return;
    const long ends[4] = {131072, 393216, 655360, 786432};
    int s = 0; long off = 0;
#pragma unroll
    for (int k = 0; k < 4; k++) {
        if (i >= ends[k]) { s = k + 1; off = ends[k]; }
    }
    g_wtf[i] = tf32r(a.p[s][i - off]);
}

// ===================== GroupNorm 1 (tf32-rounded out, [b,n,c]) ===============
__global__ void gn1_stats_k(const float* __restrict__ x) {
    int bg = blockIdx.x;
    const float* p = x + (long)bg * 8192;
    float s = 0.f, ss = 0.f;
    for (int i = threadIdx.x; i < 2048; i += 256) {
        float4 v = ((const float4*)p)[i];
        s += v.x + v.y + v.z + v.w;
        ss += v.x * v.x + v.y * v.y + v.z * v.z + v.w * v.w;
    }
    s = blockSum(s); ss = blockSum(ss);
    if (threadIdx.x == 0) {
        float mean = s * (1.f / 8192.f);
        float var  = ss * (1.f / 8192.f) - mean * mean;
        g_stats[bg * 2]     = mean;
        g_stats[bg * 2 + 1] = rsqrtf(var + 1e-5f);
    }
}
__global__ void gn1_apply_k(const float* __restrict__ x,
                            const float* __restrict__ gam,
                            const float* __restrict__ bet) {
    int idx = blockIdx.x * 256 + threadIdx.x;
    int c = idx & 255;
    int n = (idx >> 8) & 1023;
    int b = idx >> 18;
    float v = x[((long)(b * 256 + c)) * 1024 + n];
    int sg = (b << 5) | (c >> 3);
    float mean = g_stats[sg * 2], rstd = g_stats[sg * 2 + 1];
    g_xnf[idx] = tf32r((v - mean) * rstd * gam[c] + bet[c]);
}

// ===================== GroupNorm 2 (h0 fp32 -> hnb bf16) =====================
__global__ void gn2_k(const float* __restrict__ gg, const float* __restrict__ gb) {
    int b = blockIdx.x >> 5, g = blockIdx.x & 31;
    const float4* p = (const float4*)(g_h0 + (long)b * HW * INNER + g * 16);
    float s = 0.f, ss = 0.f;
    for (int i = threadIdx.x; i < HW * 4; i += 256) {
        int n = i >> 2, j = i & 3;
        float4 v = p[n * 128 + j];
        s += v.x + v.y + v.z + v.w;
        ss += v.x * v.x + v.y * v.y + v.z * v.z + v.w * v.w;
    }
    s = blockSum(s); ss = blockSum(ss);
    float mean = s * (1.f / 16384.f);
    float rstd = rsqrtf(ss * (1.f / 16384.f) - mean * mean + 1e-5f);
    __nv_bfloat16* q = g_hnb + (long)b * HW * INNER + g * 16;
    for (int i = threadIdx.x; i < HW * 4; i += 256) {
        int n = i >> 2, j = i & 3;
        int c = g * 16 + j * 4;
        float4 v = p[n * 128 + j];
        __nv_bfloat162 o0 = __floats2bfloat162_rn(
            (v.x - mean) * rstd * gg[c] + gb[c],
            (v.y - mean) * rstd * gg[c + 1] + gb[c + 1]);
        __nv_bfloat162 o1 = __floats2bfloat162_rn(
            (v.z - mean) * rstd * gg[c + 2] + gb[c + 2],
            (v.w - mean) * rstd * gg[c + 3] + gb[c + 3]);
        *(uint2*)(q + n * INNER + j * 4) = make_uint2(
            *(uint32_t*)&o0, *(uint32_t*)&o1);
    }
}

// ===================== softmax over 1024 (bf16 in/out) =======================
__global__ void softmax_k() {
    __nv_bfloat162* row = (__nv_bfloat162*)(g_attn + (long)blockIdx.x * HW);
    int t = threadIdx.x;
    __nv_bfloat162 a = row[t * 2], b = row[t * 2 + 1];
    float2 fa = __bfloat1622float2(a), fb = __bfloat1622float2(b);
    float m = blockMax(fmaxf(fmaxf(fa.x, fa.y), fmaxf(fb.x, fb.y)));
    fa.x = __expf(fa.x - m); fa.y = __expf(fa.y - m);
    fb.x = __expf(fb.x - m); fb.y = __expf(fb.y - m);
    float inv = 1.f / blockSum(fa.x + fa.y + fb.x + fb.y);
    fa.x *= inv; fa.y *= inv; fb.x *= inv; fb.y *= inv;
    row[t * 2]     = __floats2bfloat162_rn(fa.x, fa.y);
    row[t * 2 + 1] = __floats2bfloat162_rn(fb.x, fb.y);
}

// ===================== fused cross-attention (tf32-rounded fp32 out) =========
__global__ void __launch_bounds__(256) ca_attn_k() {
    __shared__ float Ks[CTXN][DH];
    __shared__ float Vs[CTXN][DH];
    int b = blockIdx.x >> 3, h = blockIdx.x & 7;
    const float* kp = g_kvc + (long)b * CTXN * 1024 + h * DH;
    for (int i = threadIdx.x; i < CTXN * DH; i += 256) {
        int j = i >> 6, d = i & 63;
        Ks[j][d] = kp[j * 1024 + d];
        Vs[j][d] = kp[j * 1024 + 512 + d];
    }
    __syncthreads();
    const float scale = 0.125f;
    int i = blockIdx.y * 256 + threadIdx.x;
    const __nv_bfloat16* qp = g_qb + ((long)(b * HW + i)) * INNER + h * DH;
    float qv[DH];
#pragma unroll
    for (int d = 0; d < DH; d += 8) {
        uint4 u = *(const uint4*)(qp + d);
        const __nv_bfloat162* h2 = (const __nv_bfloat162*)&u;
#pragma unroll
        for (int e = 0; e < 4; e++) {
            float2 f = __bfloat1622float2(h2[e]);
            qv[d + 2 * e] = f.x; qv[d + 2 * e + 1] = f.y;
        }
    }
    float l = 0.f, acc[DH];
#pragma unroll
    for (int d = 0; d < DH; d++) acc[d] = 0.f;
    for (int j = 0; j < CTXN; j++) {
        float s = 0.f;
#pragma unroll
        for (int d = 0; d < DH; d++) s += qv[d] * Ks[j][d];
        float e = __expf(s * scale);
        l += e;
#pragma unroll
        for (int d = 0; d < DH; d++) acc[d] += e * Vs[j][d];
    }
    float inv = 1.f / l;
    float* op = g_of + ((long)(b * HW + i)) * INNER + h * DH;
#pragma unroll
    for (int d = 0; d < DH; d += 4)
        *(float4*)(op + d) = make_float4(
            tf32r(acc[d] * inv), tf32r(acc[d + 1] * inv),
            tf32r(acc[d + 2] * inv), tf32r(acc[d + 3] * inv));
}

// ===================== mma.sync GEMM: 4-stage, frag double-buffered ==========
// C[bz] = alpha * A[bz] @ B[bz]^T (+ bias[n]) (+ rcoef * R)
// DT=0: bf16 (m16n8k16, BK=64).  DT=1: tf32-in-fp32 (m16n8k8, BK=32).
// A: [M,lda] row-major; B: [N,ldb] row-major. CTA 128x128, 8 warps (2x4, 64x32).
// Rows are 128B in smem, XOR-swizzled in 16B units. One sync per K-chunk.
// TOUT: store (and read R) at [bz*M*N + n*M + m]. tcf: tf32-round Cf stores.
#define STAGES  4
#define STAGE_B 32768
#define GSMEM   (STAGES * STAGE_B)

template <int DT>
__device__ __forceinline__ void frag_load(
    uint32_t aT, uint32_t bT, int wm, int wn, int lane, int kk,
    uint32_t af[4][4], uint32_t bfr[2][4]) {
    if (DT == 0) {
        const int r0 = lane & 15;
        const int uu = kk * 2 + (lane >> 4);
#pragma unroll
        for (int mi = 0; mi < 4; mi++) {
            int r = wm + mi * 16 + r0;
            ldsm_x4(af[mi], aT + r * 128 + ((uu ^ (r & 7)) << 4));
        }
#pragma unroll
        for (int p = 0; p < 2; p++) {
            int r = wn + p * 16 + r0;
            ldsm_x4(bfr[p], bT + r * 128 + ((uu ^ (r & 7)) << 4));
        }
    } else {
        // tf32: mats A = (rows0-7,u),(rows8-15,u),(rows0-7,u+1),(rows8-15,u+1)
        const int ra = (lane & 7) + ((lane >> 3) & 1) * 8;
        const int ua = kk * 2 + (lane >> 4);
        // mats B = (n0-7,u),(n0-7,u+1),(n8-15,u),(n8-15,u+1)
        const int rb = (lane & 7) + ((lane >> 4) & 1) * 8;
        const int ub = kk * 2 + ((lane >> 3) & 1);
#pragma unroll
        for (int mi = 0; mi < 4; mi++) {
            int r = wm + mi * 16 + ra;
            ldsm_x4(af[mi], aT + r * 128 + ((ua ^ (r & 7)) << 4));
        }
#pragma unroll
        for (int p = 0; p < 2; p++) {
            int r = wn + p * 16 + rb;
            ldsm_x4(bfr[p], bT + r * 128 + ((ub ^ (r & 7)) << 4));
        }
    }
}

template <int DT>
__device__ __forceinline__ void frag_mma(
    float acc[4][4][4], uint32_t af[4][4], uint32_t bfr[2][4]) {
#pragma unroll
    for (int mi = 0; mi < 4; mi++)
#pragma unroll
        for (int p = 0; p < 2; p++) {
            if (DT == 0) {
                mma_bf16(acc[mi][2 * p],     af[mi], bfr[p][0], bfr[p][2]);
                mma_bf16(acc[mi][2 * p + 1], af[mi], bfr[p][1], bfr[p][3]);
            } else {
                mma_tf32(acc[mi][2 * p],     af[mi], bfr[p][0], bfr[p][1]);
                mma_tf32(acc[mi][2 * p + 1], af[mi], bfr[p][2], bfr[p][3]);
            }
        }
}

template <int DT, bool TOUT>
__global__ void __launch_bounds__(256) gemm_mma(
    const void* __restrict__ A_, long sA, int lda,
    const void* __restrict__ B_, long sB, int ldb,
    float* __restrict__ Cf, __nv_bfloat16* __restrict__ Cb,
    const float* __restrict__ bias, const float* __restrict__ R,
    float rcoef, float alpha, int M, int N, int K, int tcf) {
    constexpr int ESZ = DT ? 4 : 2;
    constexpr int BK  = DT ? 32 : 64;
    extern __shared__ __align__(128) char sm[];
    const uint32_t sb = smem_to_u32(sm);
    const int tid  = threadIdx.x;
    const int lane = tid & 31;
    const int wid  = tid >> 5;
    const int bz = blockIdx.z;
    const int bm = blockIdx.y * 128;
    const int bn = blockIdx.x * 128;
    const int wm = (wid >> 2) * 64;
    const int wn = (wid & 3) * 32;
    const char* Ab = (const char*)A_ + (long)bz * sA * ESZ;
    const char* Bb = (const char*)B_ + (long)bz * sB * ESZ;

    float acc[4][4][4];
#pragma unroll
    for (int i = 0; i < 4; i++)
#pragma unroll
        for (int j = 0; j < 4; j++)
#pragma unroll
            for (int e = 0; e < 4; e++) acc[i][j][e] = 0.f;

    // loader: 256 threads, each does half a 128B row of A and of B (4 cp16 each)
    const int lrow = tid >> 1;
    const int lu0  = (tid & 1) * 4;
    const bool aValid = (bm + lrow) < M;
    const long aOff = aValid ? ((long)(bm + lrow) * lda) * ESZ : 0;
    const long bOff = ((long)(bn + lrow) * ldb) * ESZ;
    const int nIter = K / BK;

#define LOADC(i, s) do {                                                        \
    uint32_t dA = sb + (s) * STAGE_B + lrow * 128;                              \
    uint32_t dB = dA + 16384;                                                   \
    const char* gA = Ab + aOff + (long)(i) * 128;                               \
    const char* gB = Bb + bOff + (long)(i) * 128;                               \
    _Pragma("unroll")                                                           \
    for (int j = 0; j < 4; j++) {                                               \
        int u = lu0 + j;                                                        \
        uint32_t so = (uint32_t)((u ^ (lrow & 7)) << 4);                        \
        cp16(dA + so, gA + u * 16, aValid);                                     \
        cp16(dB + so, gB + u * 16, true);                                       \
    }                                                                           \
} while (0)

    // prologue: fill stages 0..2 (one commit group per stage, always)
#pragma unroll
    for (int i = 0; i < STAGES - 1; i++) {
        if (i < nIter) LOADC(i, i);
        CP_COMMIT();
    }
    cp_wait<STAGES - 2>();
    __syncthreads();

    uint32_t af[2][4][4], bfr[2][2][4];
    {
        const uint32_t aT = sb, bT = sb + 16384;
        frag_load<DT>(aT, bT, wm, wn, lane, 0, af[0], bfr[0]);
    }

    for (int it = 0; it < nIter; it++) {
        const int s = it & (STAGES - 1);
        const uint32_t aT = sb + s * STAGE_B;
        const uint32_t bT = aT + 16384;
#pragma unroll
        for (int kk = 0; kk < 4; kk++) {
            const int cur = kk & 1;
            if (kk == 0) {
                if (it + STAGES - 1 < nIter) LOADC(it + STAGES - 1, (it + STAGES - 1) & (STAGES - 1));
                CP_COMMIT();
            }
            if (kk < 3) {
                frag_load<DT>(aT, bT, wm, wn, lane, kk + 1, af[cur ^ 1], bfr[cur ^ 1]);
            } else if (it + 1 < nIter) {
                cp_wait<STAGES - 2>();
                __syncthreads();
                const int sn = (it + 1) & (STAGES - 1);
                frag_load<DT>(sb + sn * STAGE_B, sb + sn * STAGE_B + 16384,
                              wm, wn, lane, 0, af[cur ^ 1], bfr[cur ^ 1]);
            }
            frag_mma<DT>(acc, af[cur], bfr[cur]);
        }
    }

    // ------------------------------ epilogue ------------------------------
    const int tr = lane >> 2;
    const int tc = (lane & 3) * 2;
    const long bzMN = (long)bz * M * N;
#pragma unroll
    for (int mi = 0; mi < 4; mi++) {
#pragma unroll
        for (int r2 = 0; r2 < 2; r2++) {
            const int m = bm + wm + mi * 16 + tr + r2 * 8;
            if (m >= M) continue;
#pragma unroll
            for (int nj = 0; nj < 4; nj++) {
                const int n = bn + wn + nj * 8 + tc;
                float v0 = acc[mi][nj][r2 * 2 + 0] * alpha;
                float v1 = acc[mi][nj][r2 * 2 + 1] * alpha;
                if (bias) { v0 += bias[n]; v1 += bias[n + 1]; }
                if (TOUT) {
                    const long i0 = bzMN + (long)n * M + m;
                    const long i1 = bzMN + (long)(n + 1) * M + m;
                    if (R) { v0 += rcoef * R[i0]; v1 += rcoef * R[i1]; }
                    if (tcf) { v0 = tf32r(v0); v1 = tf32r(v1); }
                    if (Cf) { Cf[i0] = v0; Cf[i1] = v1; }
                    if (Cb) { Cb[i0] = __float2bfloat16(v0); Cb[i1] = __float2bfloat16(v1); }
                } else {
                    const long i0 = bzMN + (long)m * N + n;
                    if (R) {
                        float2 rv = *(const float2*)(R + i0);
                        v0 += rcoef * rv.x; v1 += rcoef * rv.y;
                    }
                    if (tcf) { v0 = tf32r(v0); v1 = tf32r(v1); }
                    if (Cf) *(float2*)(Cf + i0) = make_float2(v0, v1);
                    if (Cb) *(__nv_bfloat162*)(Cb + i0) = __floats2bfloat162_rn(v0, v1);
                }
            }
        }
    }
#undef LOADC
}

static void gemm(int dt, bool tout,
                 const void* A, long sA, int lda, const void* B, long sB, int ldb,
                 float* Cf, __nv_bfloat16* Cb, const float* bias, const float* R,
                 float rcoef, float alpha, int M, int N, int K, int tcf) {
    dim3 grid(N / 128, (M + 127) / 128, NB);
    if (dt == 0) {
        if (tout) {
            cudaFuncSetAttribute(gemm_mma<0, true>,  cudaFuncAttributeMaxDynamicSharedMemorySize, GSMEM);
            gemm_mma<0, true ><<<grid, 256, GSMEM>>>(A, sA, lda, B, sB, ldb, Cf, Cb, bias, R, rcoef, alpha, M, N, K, tcf);
        } else {
            cudaFuncSetAttribute(gemm_mma<0, false>, cudaFuncAttributeMaxDynamicSharedMemorySize, GSMEM);
            gemm_mma<0, false><<<grid, 256, GSMEM>>>(A, sA, lda, B, sB, ldb, Cf, Cb, bias, R, rcoef, alpha, M, N, K, tcf);
        }
    } else {
        if (tout) {
            cudaFuncSetAttribute(gemm_mma<1, true>,  cudaFuncAttributeMaxDynamicSharedMemorySize, GSMEM);
            gemm_mma<1, true ><<<grid, 256, GSMEM>>>(A, sA, lda, B, sB, ldb, Cf, Cb, bias, R, rcoef, alpha, M, N, K, tcf);
        } else {
            cudaFuncSetAttribute(gemm_mma<1, false>, cudaFuncAttributeMaxDynamicSharedMemorySize, GSMEM);
            gemm_mma<1, false><<<grid, 256, GSMEM>>>(A, sA, lda, B, sB, ldb, Cf, Cb, bias, R, rcoef, alpha, M, N, K, tcf);
        }
    }
}

// ===================== driver ================================================
extern "C" void kernel_launch(void* const* d_in, const int* in_sizes, int n_in,
                              void* d_out, int out_size) {
    const float* x      = (const float*)d_in[0];
    const float* ctx    = (const float*)d_in[1];
    const float* gn1_g  = (const float*)d_in[2];
    const float* gn1_b  = (const float*)d_in[3];
    const float* w_in   = (const float*)d_in[4];
    const float* b_in   = (const float*)d_in[5];
    const float* sa_wk  = (const float*)d_in[6];
    const float* sa_wq  = (const float*)d_in[7];
    const float* sa_wv  = (const float*)d_in[8];
    const float* sa_wp  = (const float*)d_in[9];
    const float* sa_gng = (const float*)d_in[10];
    const float* sa_gnb = (const float*)d_in[11];
    const float* ca_wq  = (const float*)d_in[12];
    const float* ca_wk  = (const float*)d_in[13];
    const float* ca_wv  = (const float*)d_in[14];
    const float* ca_wo  = (const float*)d_in[15];
    const float* ca_bo  = (const float*)d_in[16];
    const float* w_out  = (const float*)d_in[17];
    const float* b_out  = (const float*)d_in[18];
    float* out = (float*)d_out;

    float *wtf, *xnf, *h0, *h1, *of, *h2, *kvc;
    __nv_bfloat16 *wb, *hnb, *qkb, *qb, *vtb, *h1b, *attn;
    cudaGetSymbolAddress((void**)&wtf, g_wtf);
    cudaGetSymbolAddress((void**)&xnf, g_xnf);
    cudaGetSymbolAddress((void**)&h0,  g_h0);
    cudaGetSymbolAddress((void**)&h1,  g_h1);
    cudaGetSymbolAddress((void**)&of,  g_of);
    cudaGetSymbolAddress((void**)&h2,  g_h2);
    cudaGetSymbolAddress((void**)&kvc, g_kvc);
    cudaGetSymbolAddress((void**)&wb,  g_wb);
    cudaGetSymbolAddress((void**)&hnb, g_hnb);
    cudaGetSymbolAddress((void**)&qkb, g_qkb);
    cudaGetSymbolAddress((void**)&qb,  g_qb);
    cudaGetSymbolAddress((void**)&vtb, g_vtb);
    cudaGetSymbolAddress((void**)&h1b, g_h1b);
    cudaGetSymbolAddress((void**)&attn, g_attn);

    __nv_bfloat16* wb_saqk = wb + 131072;     // sa_wq | sa_wk contiguous [1024,512]
    __nv_bfloat16* wb_sav  = wb + 655360;
    __nv_bfloat16* wb_caq  = wb + 1179648;
    __nv_bfloat16* wb_cakv = wb + 1441792;    // ca_wk | ca_wv [1024,768]
    __nv_bfloat16* ctx_b   = wb + 2621440;
    float* wtf_in  = wtf;
    float* wtf_sap = wtf + 131072;
    float* wtf_cao = wtf + 393216;
    float* wtf_out = wtf + 655360;

    const float inv_sqrt_c = 0.044194173824159216f;   // 512^-0.5

    // 0. weight conversions
    CvtSrc cs;
    cs.p[0] = w_in;  cs.p[1] = sa_wq; cs.p[2] = sa_wk; cs.p[3] = sa_wv;
    cs.p[4] = sa_wp; cs.p[5] = ca_wq; cs.p[6] = ca_wk; cs.p[7] = ca_wv;
    cs.p[8] = ca_wo; cs.p[9] = w_out; cs.p[10] = ctx;
    cvt_k<<<(int)((WB_TOTAL + 255) / 256), 256>>>(cs);
    CvtTf ct;
    ct.p[0] = w_in; ct.p[1] = sa_wp; ct.p[2] = ca_wo; ct.p[3] = w_out;
    cvt_tf_k<<<(int)((WTF_TOTAL + 255) / 256), 256>>>(ct);

    // 1. GN1(x) -> xnf (tf32-rounded) [b,n,c]
    gn1_stats_k<<<NB * 32, 256>>>(x);
    gn1_apply_k<<<NB * HW * CIN / 256, 256>>>(x, gn1_g, gn1_b);
    // 2. conv_in (tf32): h0 = xn @ w_in^T + b_in (full fp32 out)
    gemm(1, false, xnf, (long)HW * CIN, CIN, wtf_in, 0, CIN, h0, nullptr,
         b_in, nullptr, 0.f, 1.f, HW, INNER, CIN, 0);
    // 3. GN2(h0) -> hnb bf16
    gn2_k<<<NB * 32, 256>>>(sa_gng, sa_gnb);
    // 4a. q|k merged (bf16): qkb = hn @ [wq;wk]^T  [b, m, 1024]
    gemm(0, false, hnb, (long)HW * INNER, INNER, wb_saqk, 0, INNER,
         nullptr, qkb, nullptr, nullptr, 0.f, 1.f, HW, 1024, INNER, 0);
    // 4b. v (bf16, transposed store)
    gemm(0, true, hnb, (long)HW * INNER, INNER, wb_sav, 0, INNER,
         nullptr, vtb, nullptr, nullptr, 0.f, 1.f, HW, INNER, INNER, 0);
    // 5. sim = q @ k^T * c^-0.5 -> attn bf16
    gemm(0, false, qkb, (long)HW * 1024, 1024, qkb + 512, (long)HW * 1024, 1024,
         nullptr, attn, nullptr, nullptr, 0.f, inv_sqrt_c, HW, HW, INNER, 0);
    // 6. softmax
    softmax_k<<<NB * HW, 256>>>();
    // 7. o = attn @ v (bf16, tf32-rounded fp32 out)
    gemm(0, false, attn, (long)HW * HW, HW, vtb, (long)INNER * HW, HW,
         of, nullptr, nullptr, nullptr, 0.f, 1.f, HW, INNER, HW, 1);
    // 8. h1 = o @ wp^T + 2*h0 (tf32; full fp32 + bf16 copies)
    gemm(1, false, of, (long)HW * INNER, INNER, wtf_sap, 0, INNER,
         h1, h1b, nullptr, h0, 2.f, 1.f, HW, INNER, INNER, 0);
    // 9. CA projections: q (bf16), fused k|v (bf16, fp32 out)
    gemm(0, false, h1b, (long)HW * INNER, INNER, wb_caq, 0, INNER,
         nullptr, qb, nullptr, nullptr, 0.f, 1.f, HW, INNER, INNER, 0);
    gemm(0, false, ctx_b, (long)CTXN * CTXD, CTXD, wb_cakv, 0, CTXD,
         kvc, nullptr, nullptr, nullptr, 0.f, 1.f, CTXN, 1024, CTXD, 0);
    // 10. fused cross-attention -> of (tf32-rounded)
    ca_attn_k<<<dim3(NB * 8, 4), 256>>>();
    // 11. h2 = o @ ca_wo^T + ca_bo + h1 (tf32; tf32-rounded out)
    gemm(1, false, of, (long)HW * INNER, INNER, wtf_cao, 0, INNER,
         h2, nullptr, ca_bo, h1, 1.f, 1.f, HW, INNER, INNER, 1);
    // 12. out = h2 @ w_out^T + b_out + x (tf32, TOUT -> NCHW)
    gemm(1, true, h2, (long)HW * INNER, INNER, wtf_out, 0, INNER,
         out, nullptr, b_out, x, 1.f, 1.f, HW, CIN, INNER, 0);
}

// round 7
// speedup vs baseline: 1.3253x; 1.1012x over previous
#include <cuda_runtime.h>
#include <cuda_bf16.h>
#include <math.h>
#include <stdint.h>

#define NB    16
#define CIN   256
#define HW    1024
#define INNER 512
#define CTXN  77
#define CTXD  768
#define DH    64

// ===================== PTX helpers (sm_80-safe only) =========================
__device__ __forceinline__ uint32_t smem_to_u32(const void* p) {
    uint32_t a;
    asm("{ .reg .u64 t; cvta.to.shared.u64 t, %1; cvt.u32.u64 %0, t; }" : "=r"(a) : "l"(p));
    return a;
}
__device__ __forceinline__ void cp16(uint32_t dst, const void* src, bool valid) {
    int sz = valid ? 16 : 0;
    asm volatile("cp.async.cg.shared.global [%0], [%1], 16, %2;"
                 :: "r"(dst), "l"(src), "r"(sz) : "memory");
}
#define CP_COMMIT() asm volatile("cp.async.commit_group;" ::: "memory")
template <int N>
__device__ __forceinline__ void cp_wait() {
    asm volatile("cp.async.wait_group %0;" :: "n"(N) : "memory");
}
__device__ __forceinline__ void ldsm_x4(uint32_t* r, uint32_t addr) {
    asm volatile("ldmatrix.sync.aligned.m8n8.x4.shared.b16 {%0,%1,%2,%3}, [%4];"
        : "=r"(r[0]), "=r"(r[1]), "=r"(r[2]), "=r"(r[3]) : "r"(addr));
}
__device__ __forceinline__ void mma_bf16(float* d, const uint32_t* a,
                                         uint32_t b0, uint32_t b1) {
    asm volatile(
        "mma.sync.aligned.m16n8k16.row.col.f32.bf16.bf16.f32 "
        "{%0,%1,%2,%3}, {%4,%5,%6,%7}, {%8,%9}, {%0,%1,%2,%3};"
        : "+f"(d[0]), "+f"(d[1]), "+f"(d[2]), "+f"(d[3])
        : "r"(a[0]), "r"(a[1]), "r"(a[2]), "r"(a[3]), "r"(b0), "r"(b1));
}
__device__ __forceinline__ void mma_tf32(float* d, const uint32_t* a,
                                         uint32_t b0, uint32_t b1) {
    asm volatile(
        "mma.sync.aligned.m16n8k8.row.col.f32.tf32.tf32.f32 "
        "{%0,%1,%2,%3}, {%4,%5,%6,%7}, {%8,%9}, {%0,%1,%2,%3};"
        : "+f"(d[0]), "+f"(d[1]), "+f"(d[2]), "+f"(d[3])
        : "r"(a[0]), "r"(a[1]), "r"(a[2]), "r"(a[3]), "r"(b0), "r"(b1));
}
__device__ __forceinline__ float tf32r(float v) {
    uint32_t r;
    asm("cvt.rna.tf32.f32 %0, %1;" : "=r"(r) : "f"(v));
    return __uint_as_float(r);
}

// ===================== scratch (device globals) ==============================
#define WB_TOTAL 3567616L
#define WTF_TOTAL 786432L
__device__ __align__(16) __nv_bfloat16 g_wb[WB_TOTAL];      // bf16 weights + ctx
__device__ __align__(16) float g_wtf[WTF_TOTAL];            // tf32 trunk weights
__device__ __align__(16) float g_xnf[NB * HW * CIN];        // GN1 out (tf32-rounded)
__device__ __align__(16) float g_h0 [NB * HW * INNER];      // conv_in out (full fp32)
__device__ __align__(16) float g_h1 [NB * HW * INNER];      // after SA (full fp32)
__device__ __align__(16) float g_of [NB * HW * INNER];      // attn outs (tf32-rounded)
__device__ __align__(16) float g_h2 [NB * HW * INNER];      // after CA (tf32-rounded)
__device__ __align__(16) float g_kvc[NB * CTXN * 1024];
__device__ float g_stats[NB * 32 * 2];
__device__ __align__(16) __nv_bfloat16 g_hnb [NB * HW * INNER];
__device__ __align__(16) __nv_bfloat16 g_qkb [NB * HW * 1024];  // q|k merged
__device__ __align__(16) __nv_bfloat16 g_qb  [NB * HW * INNER]; // CA q
__device__ __align__(16) __nv_bfloat16 g_vtb [NB * HW * INNER];
__device__ __align__(16) __nv_bfloat16 g_h1b [NB * HW * INNER];
__device__ __align__(16) __nv_bfloat16 g_attn[(long)NB * HW * HW];

// ===================== reductions ============================================
__device__ __forceinline__ float warpSum(float v) {
#pragma unroll
    for (int o = 16; o; o >>= 1) v += __shfl_xor_sync(0xffffffffu, v, o);
    return v;
}
__device__ float blockSum(float v) {
    __shared__ float sm[8];
    int t = threadIdx.x;
    v = warpSum(v);
    if ((t & 31) == 0) sm[t >> 5] = v;
    __syncthreads();
    if (t < 32) {
        float w = (t < 8) ? sm[t] : 0.f;
        w = warpSum(w);
        if (t == 0) sm[0] = w;
    }
    __syncthreads();
    float r = sm[0];
    __syncthreads();
    return r;
}
__device__ __forceinline__ float warpMax(float v) {
#pragma unroll
    for (int o = 16; o; o >>= 1) v = fmaxf(v, __shfl_xor_sync(0xffffffffu, v, o));
    return v;
}
__device__ float blockMax(float v) {
    __shared__ float sm[8];
    int t = threadIdx.x;
    v = warpMax(v);
    if ((t & 31) == 0) sm[t >> 5] = v;
    __syncthreads();
    if (t < 32) {
        float w = (t < 8) ? sm[t] : -3.0e38f;
        w = warpMax(w);
        if (t == 0) sm[0] = w;
    }
    __syncthreads();
    float r = sm[0];
    __syncthreads();
    return r;
}

// ===================== conversions ===========================================
struct CvtSrc { const float* p[11]; };
__global__ void cvt_k(CvtSrc a) {
    long i = (long)blockIdx.x * 256 + threadIdx.x;
    if (i >= WB_TOTAL) return;
    const long ends[11] = {131072, 393216, 655360, 917504, 1179648, 1441792,
                           1835008, 2228224, 2490368, 2621440, 3567616};
    int s = 0; long off = 0;
#pragma unroll
    for (int k = 0; k < 11; k++) {
        if (i >= ends[k]) { s = k + 1; off = ends[k]; }
    }
    g_wb[i] = __float2bfloat16(a.p[s][i - off]);
}
struct CvtTf { const float* p[4]; };
__global__ void cvt_tf_k(CvtTf a) {   // w_in | sa_wp | ca_wo | w_out (tf32-rounded)
    long i = (long)blockIdx.x * 256 + threadIdx.x;
    if (i >= WTF_TOTAL) return;
    const long ends[4] = {131072, 393216, 655360, 786432};
    int s = 0; long off = 0;
#pragma unroll
    for (int k = 0; k < 4; k++) {
        if (i >= ends[k]) { s = k + 1; off = ends[k]; }
    }
    g_wtf[i] = tf32r(a.p[s][i - off]);
}

// ===================== GroupNorm 1 (tf32-rounded out, [b,n,c]) ===============
__global__ void gn1_stats_k(const float* __restrict__ x) {
    int bg = blockIdx.x;
    const float* p = x + (long)bg * 8192;
    float s = 0.f, ss = 0.f;
    for (int i = threadIdx.x; i < 2048; i += 256) {
        float4 v = ((const float4*)p)[i];
        s += v.x + v.y + v.z + v.w;
        ss += v.x * v.x + v.y * v.y + v.z * v.z + v.w * v.w;
    }
    s = blockSum(s); ss = blockSum(ss);
    if (threadIdx.x == 0) {
        float mean = s * (1.f / 8192.f);
        float var  = ss * (1.f / 8192.f) - mean * mean;
        g_stats[bg * 2]     = mean;
        g_stats[bg * 2 + 1] = rsqrtf(var + 1e-5f);
    }
}
__global__ void gn1_apply_k(const float* __restrict__ x,
                            const float* __restrict__ gam,
                            const float* __restrict__ bet) {
    int idx = blockIdx.x * 256 + threadIdx.x;
    int c = idx & 255;
    int n = (idx >> 8) & 1023;
    int b = idx >> 18;
    float v = x[((long)(b * 256 + c)) * 1024 + n];
    int sg = (b << 5) | (c >> 3);
    float mean = g_stats[sg * 2], rstd = g_stats[sg * 2 + 1];
    g_xnf[idx] = tf32r((v - mean) * rstd * gam[c] + bet[c]);
}

// ===================== GroupNorm 2 (h0 fp32 -> hnb bf16) =====================
__global__ void gn2_k(const float* __restrict__ gg, const float* __restrict__ gb) {
    int b = blockIdx.x >> 5, g = blockIdx.x & 31;
    const float4* p = (const float4*)(g_h0 + (long)b * HW * INNER + g * 16);
    float s = 0.f, ss = 0.f;
    for (int i = threadIdx.x; i < HW * 4; i += 256) {
        int n = i >> 2, j = i & 3;
        float4 v = p[n * 128 + j];
        s += v.x + v.y + v.z + v.w;
        ss += v.x * v.x + v.y * v.y + v.z * v.z + v.w * v.w;
    }
    s = blockSum(s); ss = blockSum(ss);
    float mean = s * (1.f / 16384.f);
    float rstd = rsqrtf(ss * (1.f / 16384.f) - mean * mean + 1e-5f);
    __nv_bfloat16* q = g_hnb + (long)b * HW * INNER + g * 16;
    for (int i = threadIdx.x; i < HW * 4; i += 256) {
        int n = i >> 2, j = i & 3;
        int c = g * 16 + j * 4;
        float4 v = p[n * 128 + j];
        __nv_bfloat162 o0 = __floats2bfloat162_rn(
            (v.x - mean) * rstd * gg[c] + gb[c],
            (v.y - mean) * rstd * gg[c + 1] + gb[c + 1]);
        __nv_bfloat162 o1 = __floats2bfloat162_rn(
            (v.z - mean) * rstd * gg[c + 2] + gb[c + 2],
            (v.w - mean) * rstd * gg[c + 3] + gb[c + 3]);
        *(uint2*)(q + n * INNER + j * 4) = make_uint2(
            *(uint32_t*)&o0, *(uint32_t*)&o1);
    }
}

// ===================== softmax over 1024 (bf16 in/out) =======================
__global__ void softmax_k() {
    __nv_bfloat162* row = (__nv_bfloat162*)(g_attn + (long)blockIdx.x * HW);
    int t = threadIdx.x;
    __nv_bfloat162 a = row[t * 2], b = row[t * 2 + 1];
    float2 fa = __bfloat1622float2(a), fb = __bfloat1622float2(b);
    float m = blockMax(fmaxf(fmaxf(fa.x, fa.y), fmaxf(fb.x, fb.y)));
    fa.x = __expf(fa.x - m); fa.y = __expf(fa.y - m);
    fb.x = __expf(fb.x - m); fb.y = __expf(fb.y - m);
    float inv = 1.f / blockSum(fa.x + fa.y + fb.x + fb.y);
    fa.x *= inv; fa.y *= inv; fb.x *= inv; fb.y *= inv;
    row[t * 2]     = __floats2bfloat162_rn(fa.x, fa.y);
    row[t * 2 + 1] = __floats2bfloat162_rn(fb.x, fb.y);
}

// ===================== fused cross-attention (tf32-rounded fp32 out) =========
__global__ void __launch_bounds__(256) ca_attn_k() {
    __shared__ float Ks[CTXN][DH];
    __shared__ float Vs[CTXN][DH];
    int b = blockIdx.x >> 3, h = blockIdx.x & 7;
    const float* kp = g_kvc + (long)b * CTXN * 1024 + h * DH;
    for (int i = threadIdx.x; i < CTXN * DH; i += 256) {
        int j = i >> 6, d = i & 63;
        Ks[j][d] = kp[j * 1024 + d];
        Vs[j][d] = kp[j * 1024 + 512 + d];
    }
    __syncthreads();
    const float scale = 0.125f;
    int i = blockIdx.y * 256 + threadIdx.x;
    const __nv_bfloat16* qp = g_qb + ((long)(b * HW + i)) * INNER + h * DH;
    float qv[DH];
#pragma unroll
    for (int d = 0; d < DH; d += 8) {
        uint4 u = *(const uint4*)(qp + d);
        const __nv_bfloat162* h2 = (const __nv_bfloat162*)&u;
#pragma unroll
        for (int e = 0; e < 4; e++) {
            float2 f = __bfloat1622float2(h2[e]);
            qv[d + 2 * e] = f.x; qv[d + 2 * e + 1] = f.y;
        }
    }
    float l = 0.f, acc[DH];
#pragma unroll
    for (int d = 0; d < DH; d++) acc[d] = 0.f;
    for (int j = 0; j < CTXN; j++) {
        float s = 0.f;
#pragma unroll
        for (int d = 0; d < DH; d++) s += qv[d] * Ks[j][d];
        float e = __expf(s * scale);
        l += e;
#pragma unroll
        for (int d = 0; d < DH; d++) acc[d] += e * Vs[j][d];
    }
    float inv = 1.f / l;
    float* op = g_of + ((long)(b * HW + i)) * INNER + h * DH;
#pragma unroll
    for (int d = 0; d < DH; d += 4)
        *(float4*)(op + d) = make_float4(
            tf32r(acc[d] * inv), tf32r(acc[d + 1] * inv),
            tf32r(acc[d + 2] * inv), tf32r(acc[d + 3] * inv));
}

// ===================== mma.sync GEMM (R4 schedule + ldsm tf32) ===============
// C[bz] = alpha * A[bz] @ B[bz]^T (+ bias[n]) (+ rcoef * R)
// DT=0: bf16 (m16n8k16, BK=64).  DT=1: tf32-in-fp32 (m16n8k8, BK=32).
// A: [M,lda] row-major; B: [N,ldb] row-major. CTA 128x128, 8 warps (2x4, 64x32).
// 3 stages x 32KB, 2 CTAs/SM. Rows 128B, XOR-swizzled in 16B units.
// TOUT: store (and read R) at [bz*M*N + n*M + m]. tcf: tf32-round fp32 stores.
#define STAGE_B 32768
#define GSMEM   (3 * STAGE_B)

template <int DT>
__device__ __forceinline__ void frag_load(
    uint32_t aT, uint32_t bT, int wm, int wn, int lane, int kk,
    uint32_t af[4][4], uint32_t bfr[2][4]) {
    if (DT == 0) {
        const int r0 = lane & 15;
        const int uu = kk * 2 + (lane >> 4);
#pragma unroll
        for (int mi = 0; mi < 4; mi++) {
            int r = wm + mi * 16 + r0;
            ldsm_x4(af[mi], aT + r * 128 + ((uu ^ (r & 7)) << 4));
        }
#pragma unroll
        for (int p = 0; p < 2; p++) {
            int r = wn + p * 16 + r0;
            ldsm_x4(bfr[p], bT + r * 128 + ((uu ^ (r & 7)) << 4));
        }
    } else {
        const int ra = (lane & 7) + ((lane >> 3) & 1) * 8;
        const int ua = kk * 2 + (lane >> 4);
        const int rb = (lane & 7) + ((lane >> 4) & 1) * 8;
        const int ub = kk * 2 + ((lane >> 3) & 1);
#pragma unroll
        for (int mi = 0; mi < 4; mi++) {
            int r = wm + mi * 16 + ra;
            ldsm_x4(af[mi], aT + r * 128 + ((ua ^ (r & 7)) << 4));
        }
#pragma unroll
        for (int p = 0; p < 2; p++) {
            int r = wn + p * 16 + rb;
            ldsm_x4(bfr[p], bT + r * 128 + ((ub ^ (r & 7)) << 4));
        }
    }
}

template <int DT>
__device__ __forceinline__ void frag_mma(
    float acc[4][4][4], uint32_t af[4][4], uint32_t bfr[2][4]) {
#pragma unroll
    for (int mi = 0; mi < 4; mi++)
#pragma unroll
        for (int p = 0; p < 2; p++) {
            if (DT == 0) {
                mma_bf16(acc[mi][2 * p],     af[mi], bfr[p][0], bfr[p][2]);
                mma_bf16(acc[mi][2 * p + 1], af[mi], bfr[p][1], bfr[p][3]);
            } else {
                mma_tf32(acc[mi][2 * p],     af[mi], bfr[p][0], bfr[p][1]);
                mma_tf32(acc[mi][2 * p + 1], af[mi], bfr[p][2], bfr[p][3]);
            }
        }
}

template <int DT, bool TOUT>
__global__ void __launch_bounds__(256, 2) gemm_mma(
    const void* __restrict__ A_, long sA, int lda,
    const void* __restrict__ B_, long sB, int ldb,
    float* __restrict__ Cf, __nv_bfloat16* __restrict__ Cb,
    const float* __restrict__ bias, const float* __restrict__ R,
    float rcoef, float alpha, int M, int N, int K, int tcf) {
    constexpr int ESZ = DT ? 4 : 2;
    constexpr int BK  = DT ? 32 : 64;
    extern __shared__ __align__(128) char sm[];
    const uint32_t sb = smem_to_u32(sm);
    const int tid  = threadIdx.x;
    const int lane = tid & 31;
    const int wid  = tid >> 5;
    const int bz = blockIdx.z;
    const int bm = blockIdx.y * 128;
    const int bn = blockIdx.x * 128;
    const int wm = (wid >> 2) * 64;
    const int wn = (wid & 3) * 32;
    const char* Ab = (const char*)A_ + (long)bz * sA * ESZ;
    const char* Bb = (const char*)B_ + (long)bz * sB * ESZ;

    float acc[4][4][4];
#pragma unroll
    for (int i = 0; i < 4; i++)
#pragma unroll
        for (int j = 0; j < 4; j++)
#pragma unroll
            for (int e = 0; e < 4; e++) acc[i][j][e] = 0.f;

    // loader: 256 threads, each does half a 128B row of A and of B (4 cp16 each)
    const int lrow = tid >> 1;
    const int lu0  = (tid & 1) * 4;
    const bool aValid = (bm + lrow) < M;
    const long aOff = aValid ? ((long)(bm + lrow) * lda) * ESZ : 0;
    const long bOff = ((long)(bn + lrow) * ldb) * ESZ;
    const int nIter = K / BK;

#define LOADC(i, s) do {                                                        \
    uint32_t dA = sb + (s) * STAGE_B + lrow * 128;                              \
    uint32_t dB = dA + 16384;                                                   \
    const char* gA = Ab + aOff + (long)(i) * 128;                               \
    const char* gB = Bb + bOff + (long)(i) * 128;                               \
    _Pragma("unroll")                                                           \
    for (int j = 0; j < 4; j++) {                                               \
        int u = lu0 + j;                                                        \
        uint32_t so = (uint32_t)((u ^ (lrow & 7)) << 4);                        \
        cp16(dA + so, gA + u * 16, aValid);                                     \
        cp16(dB + so, gB + u * 16, true);                                       \
    }                                                                           \
} while (0)

    LOADC(0, 0); CP_COMMIT();
    if (1 < nIter) { LOADC(1, 1); }
    CP_COMMIT();

    uint32_t af[4][4], bfr[2][4];

    for (int it = 0; it < nIter; it++) {
        const int s = it % 3;
        if (it + 1 < nIter) cp_wait<1>(); else cp_wait<0>();
        __syncthreads();
        if (it + 2 < nIter) { LOADC(it + 2, (it + 2) % 3); CP_COMMIT(); }

        const uint32_t aT = sb + s * STAGE_B;
        const uint32_t bT = aT + 16384;
#pragma unroll
        for (int kk = 0; kk < 4; kk++) {
            frag_load<DT>(aT, bT, wm, wn, lane, kk, af, bfr);
            frag_mma<DT>(acc, af, bfr);
        }
        __syncthreads();
    }

    // ------------------------------ epilogue ------------------------------
    const int tr = lane >> 2;
    const int tc = (lane & 3) * 2;
    const long bzMN = (long)bz * M * N;
#pragma unroll
    for (int mi = 0; mi < 4; mi++) {
#pragma unroll
        for (int r2 = 0; r2 < 2; r2++) {
            const int m = bm + wm + mi * 16 + tr + r2 * 8;
            if (m >= M) continue;
#pragma unroll
            for (int nj = 0; nj < 4; nj++) {
                const int n = bn + wn + nj * 8 + tc;
                float v0 = acc[mi][nj][r2 * 2 + 0] * alpha;
                float v1 = acc[mi][nj][r2 * 2 + 1] * alpha;
                if (bias) { v0 += bias[n]; v1 += bias[n + 1]; }
                if (TOUT) {
                    const long i0 = bzMN + (long)n * M + m;
                    const long i1 = bzMN + (long)(n + 1) * M + m;
                    if (R) { v0 += rcoef * R[i0]; v1 += rcoef * R[i1]; }
                    if (tcf) { v0 = tf32r(v0); v1 = tf32r(v1); }
                    if (Cf) { Cf[i0] = v0; Cf[i1] = v1; }
                    if (Cb) { Cb[i0] = __float2bfloat16(v0); Cb[i1] = __float2bfloat16(v1); }
                } else {
                    const long i0 = bzMN + (long)m * N + n;
                    if (R) {
                        float2 rv = *(const float2*)(R + i0);
                        v0 += rcoef * rv.x; v1 += rcoef * rv.y;
                    }
                    if (tcf) { v0 = tf32r(v0); v1 = tf32r(v1); }
                    if (Cf) *(float2*)(Cf + i0) = make_float2(v0, v1);
                    if (Cb) *(__nv_bfloat162*)(Cb + i0) = __floats2bfloat162_rn(v0, v1);
                }
            }
        }
    }
#undef LOADC
}

static void gemm(int dt, bool tout,
                 const void* A, long sA, int lda, const void* B, long sB, int ldb,
                 float* Cf, __nv_bfloat16* Cb, const float* bias, const float* R,
                 float rcoef, float alpha, int M, int N, int K, int tcf) {
    dim3 grid(N / 128, (M + 127) / 128, NB);
    if (dt == 0) {
        if (tout) {
            cudaFuncSetAttribute(gemm_mma<0, true>,  cudaFuncAttributeMaxDynamicSharedMemorySize, GSMEM);
            gemm_mma<0, true ><<<grid, 256, GSMEM>>>(A, sA, lda, B, sB, ldb, Cf, Cb, bias, R, rcoef, alpha, M, N, K, tcf);
        } else {
            cudaFuncSetAttribute(gemm_mma<0, false>, cudaFuncAttributeMaxDynamicSharedMemorySize, GSMEM);
            gemm_mma<0, false><<<grid, 256, GSMEM>>>(A, sA, lda, B, sB, ldb, Cf, Cb, bias, R, rcoef, alpha, M, N, K, tcf);
        }
    } else {
        if (tout) {
            cudaFuncSetAttribute(gemm_mma<1, true>,  cudaFuncAttributeMaxDynamicSharedMemorySize, GSMEM);
            gemm_mma<1, true ><<<grid, 256, GSMEM>>>(A, sA, lda, B, sB, ldb, Cf, Cb, bias, R, rcoef, alpha, M, N, K, tcf);
        } else {
            cudaFuncSetAttribute(gemm_mma<1, false>, cudaFuncAttributeMaxDynamicSharedMemorySize, GSMEM);
            gemm_mma<1, false><<<grid, 256, GSMEM>>>(A, sA, lda, B, sB, ldb, Cf, Cb, bias, R, rcoef, alpha, M, N, K, tcf);
        }
    }
}

// ===================== driver ================================================
extern "C" void kernel_launch(void* const* d_in, const int* in_sizes, int n_in,
                              void* d_out, int out_size) {
    const float* x      = (const float*)d_in[0];
    const float* ctx    = (const float*)d_in[1];
    const float* gn1_g  = (const float*)d_in[2];
    const float* gn1_b  = (const float*)d_in[3];
    const float* w_in   = (const float*)d_in[4];
    const float* b_in   = (const float*)d_in[5];
    const float* sa_wk  = (const float*)d_in[6];
    const float* sa_wq  = (const float*)d_in[7];
    const float* sa_wv  = (const float*)d_in[8];
    const float* sa_wp  = (const float*)d_in[9];
    const float* sa_gng = (const float*)d_in[10];
    const float* sa_gnb = (const float*)d_in[11];
    const float* ca_wq  = (const float*)d_in[12];
    const float* ca_wk  = (const float*)d_in[13];
    const float* ca_wv  = (const float*)d_in[14];
    const float* ca_wo  = (const float*)d_in[15];
    const float* ca_bo  = (const float*)d_in[16];
    const float* w_out  = (const float*)d_in[17];
    const float* b_out  = (const float*)d_in[18];
    float* out = (float*)d_out;

    float *wtf, *xnf, *h0, *h1, *of, *h2, *kvc;
    __nv_bfloat16 *wb, *hnb, *qkb, *qb, *vtb, *h1b, *attn;
    cudaGetSymbolAddress((void**)&wtf, g_wtf);
    cudaGetSymbolAddress((void**)&xnf, g_xnf);
    cudaGetSymbolAddress((void**)&h0,  g_h0);
    cudaGetSymbolAddress((void**)&h1,  g_h1);
    cudaGetSymbolAddress((void**)&of,  g_of);
    cudaGetSymbolAddress((void**)&h2,  g_h2);
    cudaGetSymbolAddress((void**)&kvc, g_kvc);
    cudaGetSymbolAddress((void**)&wb,  g_wb);
    cudaGetSymbolAddress((void**)&hnb, g_hnb);
    cudaGetSymbolAddress((void**)&qkb, g_qkb);
    cudaGetSymbolAddress((void**)&qb,  g_qb);
    cudaGetSymbolAddress((void**)&vtb, g_vtb);
    cudaGetSymbolAddress((void**)&h1b, g_h1b);
    cudaGetSymbolAddress((void**)&attn, g_attn);

    __nv_bfloat16* wb_saqk = wb + 131072;     // sa_wq | sa_wk contiguous [1024,512]
    __nv_bfloat16* wb_sav  = wb + 655360;
    __nv_bfloat16* wb_caq  = wb + 1179648;
    __nv_bfloat16* wb_cakv = wb + 1441792;    // ca_wk | ca_wv [1024,768]
    __nv_bfloat16* ctx_b   = wb + 2621440;
    float* wtf_in  = wtf;
    float* wtf_sap = wtf + 131072;
    float* wtf_cao = wtf + 393216;
    float* wtf_out = wtf + 655360;

    const float inv_sqrt_c = 0.044194173824159216f;   // 512^-0.5

    // 0. weight conversions
    CvtSrc cs;
    cs.p[0] = w_in;  cs.p[1] = sa_wq; cs.p[2] = sa_wk; cs.p[3] = sa_wv;
    cs.p[4] = sa_wp; cs.p[5] = ca_wq; cs.p[6] = ca_wk; cs.p[7] = ca_wv;
    cs.p[8] = ca_wo; cs.p[9] = w_out; cs.p[10] = ctx;
    cvt_k<<<(int)((WB_TOTAL + 255) / 256), 256>>>(cs);
    CvtTf ct;
    ct.p[0] = w_in; ct.p[1] = sa_wp; ct.p[2] = ca_wo; ct.p[3] = w_out;
    cvt_tf_k<<<(int)((WTF_TOTAL + 255) / 256), 256>>>(ct);

    // 1. GN1(x) -> xnf (tf32-rounded) [b,n,c]
    gn1_stats_k<<<NB * 32, 256>>>(x);
    gn1_apply_k<<<NB * HW * CIN / 256, 256>>>(x, gn1_g, gn1_b);
    // 2. conv_in (tf32): h0 = xn @ w_in^T + b_in (full fp32 out)
    gemm(1, false, xnf, (long)HW * CIN, CIN, wtf_in, 0, CIN, h0, nullptr,
         b_in, nullptr, 0.f, 1.f, HW, INNER, CIN, 0);
    // 3. GN2(h0) -> hnb bf16
    gn2_k<<<NB * 32, 256>>>(sa_gng, sa_gnb);
    // 4a. q|k merged (bf16): qkb = hn @ [wq;wk]^T  [b, m, 1024]
    gemm(0, false, hnb, (long)HW * INNER, INNER, wb_saqk, 0, INNER,
         nullptr, qkb, nullptr, nullptr, 0.f, 1.f, HW, 1024, INNER, 0);
    // 4b. v (bf16, transposed store)
    gemm(0, true, hnb, (long)HW * INNER, INNER, wb_sav, 0, INNER,
         nullptr, vtb, nullptr, nullptr, 0.f, 1.f, HW, INNER, INNER, 0);
    // 5. sim = q @ k^T * c^-0.5 -> attn bf16
    gemm(0, false, qkb, (long)HW * 1024, 1024, qkb + 512, (long)HW * 1024, 1024,
         nullptr, attn, nullptr, nullptr, 0.f, inv_sqrt_c, HW, HW, INNER, 0);
    // 6. softmax
    softmax_k<<<NB * HW, 256>>>();
    // 7. o = attn @ v (bf16, tf32-rounded fp32 out)
    gemm(0, false, attn, (long)HW * HW, HW, vtb, (long)INNER * HW, HW,
         of, nullptr, nullptr, nullptr, 0.f, 1.f, HW, INNER, HW, 1);
    // 8. h1 = o @ wp^T + 2*h0 (tf32; full fp32 + bf16 copies)
    gemm(1, false, of, (long)HW * INNER, INNER, wtf_sap, 0, INNER,
         h1, h1b, nullptr, h0, 2.f, 1.f, HW, INNER, INNER, 0);
    // 9. CA projections: q (bf16), fused k|v (bf16, fp32 out)
    gemm(0, false, h1b, (long)HW * INNER, INNER, wb_caq, 0, INNER,
         nullptr, qb, nullptr, nullptr, 0.f, 1.f, HW, INNER, INNER, 0);
    gemm(0, false, ctx_b, (long)CTXN * CTXD, CTXD, wb_cakv, 0, CTXD,
         kvc, nullptr, nullptr, nullptr, 0.f, 1.f, CTXN, 1024, CTXD, 0);
    // 10. fused cross-attention -> of (tf32-rounded)
    ca_attn_k<<<dim3(NB * 8, 4), 256>>>();
    // 11. h2 = o @ ca_wo^T + ca_bo + h1 (tf32; tf32-rounded out)
    gemm(1, false, of, (long)HW * INNER, INNER, wtf_cao, 0, INNER,
         h2, nullptr, ca_bo, h1, 1.f, 1.f, HW, INNER, INNER, 1);
    // 12. out = h2 @ w_out^T + b_out + x (tf32, TOUT -> NCHW)
    gemm(1, true, h2, (long)HW * INNER, INNER, wtf_out, 0, INNER,
         out, nullptr, b_out, x, 1.f, 1.f, HW, CIN, INNER, 0);
}

// round 8
// speedup vs baseline: 1.5386x; 1.1610x over previous
#include <cuda_runtime.h>
#include <cuda_fp16.h>
#include <math.h>
#include <stdint.h>

#define NB    16
#define CIN   256
#define HW    1024
#define INNER 512
#define CTXN  77
#define CTXD  768
#define DH    64

// ===================== PTX helpers (sm_80-safe only) =========================
__device__ __forceinline__ uint32_t smem_to_u32(const void* p) {
    uint32_t a;
    asm("{ .reg .u64 t; cvta.to.shared.u64 t, %1; cvt.u32.u64 %0, t; }" : "=r"(a) : "l"(p));
    return a;
}
__device__ __forceinline__ void cp16(uint32_t dst, const void* src, bool valid) {
    int sz = valid ? 16 : 0;
    asm volatile("cp.async.cg.shared.global [%0], [%1], 16, %2;"
                 :: "r"(dst), "l"(src), "r"(sz) : "memory");
}
#define CP_COMMIT() asm volatile("cp.async.commit_group;" ::: "memory")
template <int N>
__device__ __forceinline__ void cp_wait() {
    asm volatile("cp.async.wait_group %0;" :: "n"(N) : "memory");
}
__device__ __forceinline__ void ldsm_x4(uint32_t* r, uint32_t addr) {
    asm volatile("ldmatrix.sync.aligned.m8n8.x4.shared.b16 {%0,%1,%2,%3}, [%4];"
        : "=r"(r[0]), "=r"(r[1]), "=r"(r[2]), "=r"(r[3]) : "r"(addr));
}
__device__ __forceinline__ void mma_f16(float* d, const uint32_t* a,
                                        uint32_t b0, uint32_t b1) {
    asm volatile(
        "mma.sync.aligned.m16n8k16.row.col.f32.f16.f16.f32 "
        "{%0,%1,%2,%3}, {%4,%5,%6,%7}, {%8,%9}, {%0,%1,%2,%3};"
        : "+f"(d[0]), "+f"(d[1]), "+f"(d[2]), "+f"(d[3])
        : "r"(a[0]), "r"(a[1]), "r"(a[2]), "r"(a[3]), "r"(b0), "r"(b1));
}

// ===================== scratch (device globals) ==============================
#define WH_TOTAL 3567616L
__device__ __align__(16) __half g_wh[WH_TOTAL];            // fp16 weights + ctx
__device__ __align__(16) float g_h0 [NB * HW * INNER];     // conv_in out (fp32)
__device__ __align__(16) float g_h1 [NB * HW * INNER];     // after SA (fp32)
__device__ __align__(16) float g_kvc[NB * CTXN * 1024];
__device__ float g_stats[NB * 32 * 2];
__device__ __align__(16) __half g_xnh [NB * HW * CIN];
__device__ __align__(16) __half g_hnh [NB * HW * INNER];
__device__ __align__(16) __half g_qkh [NB * HW * 1024];    // q|k merged
__device__ __align__(16) __half g_qh  [NB * HW * INNER];   // CA q
__device__ __align__(16) __half g_vth [NB * HW * INNER];   // v^T
__device__ __align__(16) __half g_oh  [NB * HW * INNER];   // SA attn out
__device__ __align__(16) __half g_h1h [NB * HW * INNER];
__device__ __align__(16) __half g_h2h [NB * HW * INNER];
__device__ __align__(16) __half g_ofh [NB * HW * INNER];   // CA attn out
__device__ __align__(16) __half g_attn[(long)NB * HW * HW];

// ===================== reductions ============================================
__device__ __forceinline__ float warpSum(float v) {
#pragma unroll
    for (int o = 16; o; o >>= 1) v += __shfl_xor_sync(0xffffffffu, v, o);
    return v;
}
__device__ float blockSum(float v) {
    __shared__ float sm[8];
    int t = threadIdx.x;
    v = warpSum(v);
    if ((t & 31) == 0) sm[t >> 5] = v;
    __syncthreads();
    if (t < 32) {
        float w = (t < 8) ? sm[t] : 0.f;
        w = warpSum(w);
        if (t == 0) sm[0] = w;
    }
    __syncthreads();
    float r = sm[0];
    __syncthreads();
    return r;
}
__device__ __forceinline__ float warpMax(float v) {
#pragma unroll
    for (int o = 16; o; o >>= 1) v = fmaxf(v, __shfl_xor_sync(0xffffffffu, v, o));
    return v;
}
__device__ float blockMax(float v) {
    __shared__ float sm[8];
    int t = threadIdx.x;
    v = warpMax(v);
    if ((t & 31) == 0) sm[t >> 5] = v;
    __syncthreads();
    if (t < 32) {
        float w = (t < 8) ? sm[t] : -3.0e38f;
        w = warpMax(w);
        if (t == 0) sm[0] = w;
    }
    __syncthreads();
    float r = sm[0];
    __syncthreads();
    return r;
}

// ===================== conversions ===========================================
struct CvtSrc { const float* p[11]; };
__global__ void cvt_k(CvtSrc a) {
    long i = (long)blockIdx.x * 256 + threadIdx.x;
    if (i >= WH_TOTAL) return;
    const long ends[11] = {131072, 393216, 655360, 917504, 1179648, 1441792,
                           1835008, 2228224, 2490368, 2621440, 3567616};
    int s = 0; long off = 0;
#pragma unroll
    for (int k = 0; k < 11; k++) {
        if (i >= ends[k]) { s = k + 1; off = ends[k]; }
    }
    g_wh[i] = __float2half_rn(a.p[s][i - off]);
}

// ===================== GroupNorm 1 ===========================================
__global__ void gn1_stats_k(const float* __restrict__ x) {
    int bg = blockIdx.x;
    const float* p = x + (long)bg * 8192;
    float s = 0.f, ss = 0.f;
    for (int i = threadIdx.x; i < 2048; i += 256) {
        float4 v = ((const float4*)p)[i];
        s += v.x + v.y + v.z + v.w;
        ss += v.x * v.x + v.y * v.y + v.z * v.z + v.w * v.w;
    }
    s = blockSum(s); ss = blockSum(ss);
    if (threadIdx.x == 0) {
        float mean = s * (1.f / 8192.f);
        float var  = ss * (1.f / 8192.f) - mean * mean;
        g_stats[bg * 2]     = mean;
        g_stats[bg * 2 + 1] = rsqrtf(var + 1e-5f);
    }
}
// tiled transpose + normalize: x [b][c][n] fp32 -> xnh [b][n][c] fp16
__global__ void gn1_apply_k(const float* __restrict__ x,
                            const float* __restrict__ gam,
                            const float* __restrict__ bet) {
    __shared__ float t[32][33];
    int b = blockIdx.z;
    int c0 = blockIdx.y * 32;
    int n0 = blockIdx.x * 32;
    int tx = threadIdx.x, ty = threadIdx.y;
#pragma unroll
    for (int i = 0; i < 4; i++) {
        int c = c0 + ty + i * 8;
        float v = x[((long)(b * 256 + c) << 10) + n0 + tx];
        int sg = (b << 5) | (c >> 3);
        t[ty + i * 8][tx] = (v - g_stats[sg * 2]) * g_stats[sg * 2 + 1] * gam[c] + bet[c];
    }
    __syncthreads();
#pragma unroll
    for (int i = 0; i < 4; i++) {
        int n = n0 + ty + i * 8;
        g_xnh[((long)(b * 1024 + n) << 8) + c0 + tx] = __float2half_rn(t[tx][ty + i * 8]);
    }
}

// ===================== GroupNorm 2 (h0 fp32 -> hnh fp16) =====================
__global__ void gn2_k(const float* __restrict__ gg, const float* __restrict__ gb) {
    int b = blockIdx.x >> 5, g = blockIdx.x & 31;
    const float4* p = (const float4*)(g_h0 + (long)b * HW * INNER + g * 16);
    float s = 0.f, ss = 0.f;
    for (int i = threadIdx.x; i < HW * 4; i += 256) {
        int n = i >> 2, j = i & 3;
        float4 v = p[n * 128 + j];
        s += v.x + v.y + v.z + v.w;
        ss += v.x * v.x + v.y * v.y + v.z * v.z + v.w * v.w;
    }
    s = blockSum(s); ss = blockSum(ss);
    float mean = s * (1.f / 16384.f);
    float rstd = rsqrtf(ss * (1.f / 16384.f) - mean * mean + 1e-5f);
    __half* q = g_hnh + (long)b * HW * INNER + g * 16;
    for (int i = threadIdx.x; i < HW * 4; i += 256) {
        int n = i >> 2, j = i & 3;
        int c = g * 16 + j * 4;
        float4 v = p[n * 128 + j];
        __half2 o0 = __floats2half2_rn(
            (v.x - mean) * rstd * gg[c] + gb[c],
            (v.y - mean) * rstd * gg[c + 1] + gb[c + 1]);
        __half2 o1 = __floats2half2_rn(
            (v.z - mean) * rstd * gg[c + 2] + gb[c + 2],
            (v.w - mean) * rstd * gg[c + 3] + gb[c + 3]);
        *(uint2*)(q + n * INNER + j * 4) = make_uint2(
            *(uint32_t*)&o0, *(uint32_t*)&o1);
    }
}

// ===================== softmax over 1024 (fp16 in/out) =======================
__global__ void softmax_k() {
    __half2* row = (__half2*)(g_attn + (long)blockIdx.x * HW);
    int t = threadIdx.x;
    __half2 a = row[t * 2], b = row[t * 2 + 1];
    float2 fa = __half22float2(a), fb = __half22float2(b);
    float m = blockMax(fmaxf(fmaxf(fa.x, fa.y), fmaxf(fb.x, fb.y)));
    fa.x = __expf(fa.x - m); fa.y = __expf(fa.y - m);
    fb.x = __expf(fb.x - m); fb.y = __expf(fb.y - m);
    float inv = 1.f / blockSum(fa.x + fa.y + fb.x + fb.y);
    fa.x *= inv; fa.y *= inv; fb.x *= inv; fb.y *= inv;
    row[t * 2]     = __floats2half2_rn(fa.x, fa.y);
    row[t * 2 + 1] = __floats2half2_rn(fb.x, fb.y);
}

// ===================== fused cross-attention (fp16 out) ======================
__global__ void __launch_bounds__(256) ca_attn_k() {
    __shared__ float Ks[CTXN][DH];
    __shared__ float Vs[CTXN][DH];
    int b = blockIdx.x >> 3, h = blockIdx.x & 7;
    const float* kp = g_kvc + (long)b * CTXN * 1024 + h * DH;
    for (int i = threadIdx.x; i < CTXN * DH; i += 256) {
        int j = i >> 6, d = i & 63;
        Ks[j][d] = kp[j * 1024 + d];
        Vs[j][d] = kp[j * 1024 + 512 + d];
    }
    __syncthreads();
    const float scale = 0.125f;
    int i = blockIdx.y * 256 + threadIdx.x;
    const __half* qp = g_qh + ((long)(b * HW + i)) * INNER + h * DH;
    float qv[DH];
#pragma unroll
    for (int d = 0; d < DH; d += 8) {
        uint4 u = *(const uint4*)(qp + d);
        const __half2* h2 = (const __half2*)&u;
#pragma unroll
        for (int e = 0; e < 4; e++) {
            float2 f = __half22float2(h2[e]);
            qv[d + 2 * e] = f.x; qv[d + 2 * e + 1] = f.y;
        }
    }
    float l = 0.f, acc[DH];
#pragma unroll
    for (int d = 0; d < DH; d++) acc[d] = 0.f;
    for (int j = 0; j < CTXN; j++) {
        float s = 0.f;
#pragma unroll
        for (int d = 0; d < DH; d++) s += qv[d] * Ks[j][d];
        float e = __expf(s * scale);
        l += e;
#pragma unroll
        for (int d = 0; d < DH; d++) acc[d] += e * Vs[j][d];
    }
    float inv = 1.f / l;
    __half* op = g_ofh + ((long)(b * HW + i)) * INNER + h * DH;
#pragma unroll
    for (int d = 0; d < DH; d += 8) {
        __half2 pk[4];
#pragma unroll
        for (int e = 0; e < 4; e++)
            pk[e] = __floats2half2_rn(acc[d + 2 * e] * inv, acc[d + 2 * e + 1] * inv);
        *(uint4*)(op + d) = *(uint4*)pk;
    }
}

// ===================== fp16 mma.sync GEMM (R4 schedule) ======================
// C[bz] = alpha * A[bz] @ B[bz]^T (+ bias[n]) (+ rcoef * R)
// A: fp16 [M,lda] row-major; B: fp16 [N,ldb] row-major.
// CTA 128x128, 8 warps (2x4, 64x32), BK=64, 3 stages x 32KB, 2 CTAs/SM.
// TOUT: C transposed per batch [N, M]; epilogue staged via smem, coalesced.
#define STAGE_B 32768
#define GSMEM   98304

__device__ __forceinline__ void frag_load(
    uint32_t aT, uint32_t bT, int wm, int wn, int lane, int kk,
    uint32_t af[4][4], uint32_t bfr[2][4]) {
    const int r0 = lane & 15;
    const int uu = kk * 2 + (lane >> 4);
#pragma unroll
    for (int mi = 0; mi < 4; mi++) {
        int r = wm + mi * 16 + r0;
        ldsm_x4(af[mi], aT + r * 128 + ((uu ^ (r & 7)) << 4));
    }
#pragma unroll
    for (int p = 0; p < 2; p++) {
        int r = wn + p * 16 + r0;
        ldsm_x4(bfr[p], bT + r * 128 + ((uu ^ (r & 7)) << 4));
    }
}

template <bool TOUT>
__global__ void __launch_bounds__(256, 2) gemm_mma(
    const __half* __restrict__ A_, long sA, int lda,
    const __half* __restrict__ B_, long sB, int ldb,
    float* __restrict__ Cf, __half* __restrict__ Cb,
    const float* __restrict__ bias, const float* __restrict__ R,
    float rcoef, float alpha, int M, int N, int K) {
    extern __shared__ __align__(128) char sm[];
    const uint32_t sb = smem_to_u32(sm);
    const int tid  = threadIdx.x;
    const int lane = tid & 31;
    const int wid  = tid >> 5;
    const int bz = blockIdx.z;
    const int bm = blockIdx.y * 128;
    const int bn = blockIdx.x * 128;
    const int wm = (wid >> 2) * 64;
    const int wn = (wid & 3) * 32;
    const __half* Ab = A_ + (long)bz * sA;
    const __half* Bb = B_ + (long)bz * sB;

    float acc[4][4][4];
#pragma unroll
    for (int i = 0; i < 4; i++)
#pragma unroll
        for (int j = 0; j < 4; j++)
#pragma unroll
            for (int e = 0; e < 4; e++) acc[i][j][e] = 0.f;

    const int lrow = tid >> 1;
    const int lu0  = (tid & 1) * 4;
    const bool aValid = (bm + lrow) < M;
    const long aOff = aValid ? (long)(bm + lrow) * lda : 0;
    const long bOff = (long)(bn + lrow) * ldb;
    const int nIter = K >> 6;

#define LOADC(i, s) do {                                                        \
    uint32_t dA = sb + (s) * STAGE_B + lrow * 128;                              \
    uint32_t dB = dA + 16384;                                                   \
    const __half* gA = Ab + aOff + ((long)(i) << 6);                            \
    const __half* gB = Bb + bOff + ((long)(i) << 6);                            \
    _Pragma("unroll")                                                           \
    for (int j = 0; j < 4; j++) {                                               \
        int u = lu0 + j;                                                        \
        uint32_t so = (uint32_t)((u ^ (lrow & 7)) << 4);                        \
        cp16(dA + so, gA + u * 8, aValid);                                      \
        cp16(dB + so, gB + u * 8, true);                                        \
    }                                                                           \
} while (0)

    LOADC(0, 0); CP_COMMIT();
    if (1 < nIter) { LOADC(1, 1); }
    CP_COMMIT();

    uint32_t af[4][4], bfr[2][4];

    for (int it = 0; it < nIter; it++) {
        const int s = it % 3;
        if (it + 1 < nIter) cp_wait<1>(); else cp_wait<0>();
        __syncthreads();
        if (it + 2 < nIter) { LOADC(it + 2, (it + 2) % 3); CP_COMMIT(); }

        const uint32_t aT = sb + s * STAGE_B;
        const uint32_t bT = aT + 16384;
#pragma unroll
        for (int kk = 0; kk < 4; kk++) {
            frag_load(aT, bT, wm, wn, lane, kk, af, bfr);
#pragma unroll
            for (int mi = 0; mi < 4; mi++)
#pragma unroll
                for (int p = 0; p < 2; p++) {
                    mma_f16(acc[mi][2 * p],     af[mi], bfr[p][0], bfr[p][2]);
                    mma_f16(acc[mi][2 * p + 1], af[mi], bfr[p][1], bfr[p][3]);
                }
        }
        __syncthreads();
    }

    // ------------------------------ epilogue ------------------------------
    const int tr = lane >> 2;
    const int tc = (lane & 3) * 2;
    const long bzMN = (long)bz * M * N;
    if (TOUT) {
        // stage tile [n_local][m_local] in smem (132-float rows), write coalesced
        float* st = (float*)sm;
#pragma unroll
        for (int mi = 0; mi < 4; mi++)
#pragma unroll
            for (int r2 = 0; r2 < 2; r2++) {
                const int ml = wm + mi * 16 + tr + r2 * 8;
#pragma unroll
                for (int nj = 0; nj < 4; nj++) {
                    const int nl = wn + nj * 8 + tc;
                    st[nl * 132 + ml]       = acc[mi][nj][r2 * 2 + 0] * alpha;
                    st[(nl + 1) * 132 + ml] = acc[mi][nj][r2 * 2 + 1] * alpha;
                }
            }
        __syncthreads();
#pragma unroll
        for (int r = 0; r < 16; r++) {
            const int nl = wid * 16 + r;
            const int n = bn + nl;
            float bv = bias ? bias[n] : 0.f;
            float4 v = *(float4*)&st[nl * 132 + lane * 4];
            v.x += bv; v.y += bv; v.z += bv; v.w += bv;
            const long i0 = bzMN + (long)n * M + bm + lane * 4;
            if (R) {
                float4 rv = *(const float4*)(R + i0);
                v.x += rcoef * rv.x; v.y += rcoef * rv.y;
                v.z += rcoef * rv.z; v.w += rcoef * rv.w;
            }
            if (Cf) *(float4*)(Cf + i0) = v;
            if (Cb) {
                __half2 h0 = __floats2half2_rn(v.x, v.y);
                __half2 h1 = __floats2half2_rn(v.z, v.w);
                *(uint2*)(Cb + i0) = make_uint2(*(uint32_t*)&h0, *(uint32_t*)&h1);
            }
        }
    } else {
#pragma unroll
        for (int mi = 0; mi < 4; mi++) {
#pragma unroll
            for (int r2 = 0; r2 < 2; r2++) {
                const int m = bm + wm + mi * 16 + tr + r2 * 8;
                if (m >= M) continue;
#pragma unroll
                for (int nj = 0; nj < 4; nj++) {
                    const int n = bn + wn + nj * 8 + tc;
                    float v0 = acc[mi][nj][r2 * 2 + 0] * alpha;
                    float v1 = acc[mi][nj][r2 * 2 + 1] * alpha;
                    if (bias) { v0 += bias[n]; v1 += bias[n + 1]; }
                    const long i0 = bzMN + (long)m * N + n;
                    if (R) {
                        float2 rv = *(const float2*)(R + i0);
                        v0 += rcoef * rv.x; v1 += rcoef * rv.y;
                    }
                    if (Cf) *(float2*)(Cf + i0) = make_float2(v0, v1);
                    if (Cb) {
                        __half2 hv = __floats2half2_rn(v0, v1);
                        *(uint32_t*)(Cb + i0) = *(uint32_t*)&hv;
                    }
                }
            }
        }
    }
#undef LOADC
}

static void gemm(bool tout,
                 const __half* A, long sA, int lda, const __half* B, long sB, int ldb,
                 float* Cf, __half* Cb, const float* bias, const float* R,
                 float rcoef, float alpha, int M, int N, int K) {
    dim3 grid(N / 128, (M + 127) / 128, NB);
    if (tout) {
        cudaFuncSetAttribute(gemm_mma<true>,  cudaFuncAttributeMaxDynamicSharedMemorySize, GSMEM);
        gemm_mma<true ><<<grid, 256, GSMEM>>>(A, sA, lda, B, sB, ldb, Cf, Cb, bias, R, rcoef, alpha, M, N, K);
    } else {
        cudaFuncSetAttribute(gemm_mma<false>, cudaFuncAttributeMaxDynamicSharedMemorySize, GSMEM);
        gemm_mma<false><<<grid, 256, GSMEM>>>(A, sA, lda, B, sB, ldb, Cf, Cb, bias, R, rcoef, alpha, M, N, K);
    }
}

// ===================== driver ================================================
extern "C" void kernel_launch(void* const* d_in, const int* in_sizes, int n_in,
                              void* d_out, int out_size) {
    const float* x      = (const float*)d_in[0];
    const float* ctx    = (const float*)d_in[1];
    const float* gn1_g  = (const float*)d_in[2];
    const float* gn1_b  = (const float*)d_in[3];
    const float* w_in   = (const float*)d_in[4];
    const float* b_in   = (const float*)d_in[5];
    const float* sa_wk  = (const float*)d_in[6];
    const float* sa_wq  = (const float*)d_in[7];
    const float* sa_wv  = (const float*)d_in[8];
    const float* sa_wp  = (const float*)d_in[9];
    const float* sa_gng = (const float*)d_in[10];
    const float* sa_gnb = (const float*)d_in[11];
    const float* ca_wq  = (const float*)d_in[12];
    const float* ca_wk  = (const float*)d_in[13];
    const float* ca_wv  = (const float*)d_in[14];
    const float* ca_wo  = (const float*)d_in[15];
    const float* ca_bo  = (const float*)d_in[16];
    const float* w_out  = (const float*)d_in[17];
    const float* b_out  = (const float*)d_in[18];
    float* out = (float*)d_out;

    float *h0, *h1, *kvc;
    __half *wh, *xnh, *hnh, *qkh, *qh, *vth, *oh, *h1h, *h2h, *ofh, *attnh;
    cudaGetSymbolAddress((void**)&h0,  g_h0);
    cudaGetSymbolAddress((void**)&h1,  g_h1);
    cudaGetSymbolAddress((void**)&kvc, g_kvc);
    cudaGetSymbolAddress((void**)&wh,  g_wh);
    cudaGetSymbolAddress((void**)&xnh, g_xnh);
    cudaGetSymbolAddress((void**)&hnh, g_hnh);
    cudaGetSymbolAddress((void**)&qkh, g_qkh);
    cudaGetSymbolAddress((void**)&qh,  g_qh);
    cudaGetSymbolAddress((void**)&vth, g_vth);
    cudaGetSymbolAddress((void**)&oh,  g_oh);
    cudaGetSymbolAddress((void**)&h1h, g_h1h);
    cudaGetSymbolAddress((void**)&h2h, g_h2h);
    cudaGetSymbolAddress((void**)&ofh, g_ofh);
    cudaGetSymbolAddress((void**)&attnh, g_attn);

    __half* wh_in   = wh;
    __half* wh_saqk = wh + 131072;     // sa_wq | sa_wk contiguous [1024,512]
    __half* wh_sav  = wh + 655360;
    __half* wh_sap  = wh + 917504;
    __half* wh_caq  = wh + 1179648;
    __half* wh_cakv = wh + 1441792;    // ca_wk | ca_wv [1024,768]
    __half* wh_cao  = wh + 2228224;
    __half* wh_out  = wh + 2490368;
    __half* ctx_h   = wh + 2621440;

    const float inv_sqrt_c = 0.044194173824159216f;   // 512^-0.5

    // 0. convert weights + ctx to fp16
    CvtSrc cs;
    cs.p[0] = w_in;  cs.p[1] = sa_wq; cs.p[2] = sa_wk; cs.p[3] = sa_wv;
    cs.p[4] = sa_wp; cs.p[5] = ca_wq; cs.p[6] = ca_wk; cs.p[7] = ca_wv;
    cs.p[8] = ca_wo; cs.p[9] = w_out; cs.p[10] = ctx;
    cvt_k<<<(int)((WH_TOTAL + 255) / 256), 256>>>(cs);

    // 1. GN1(x) -> xnh fp16 [b,n,c] (tiled transpose)
    gn1_stats_k<<<NB * 32, 256>>>(x);
    gn1_apply_k<<<dim3(32, 8, NB), dim3(32, 8)>>>(x, gn1_g, gn1_b);
    // 2. conv_in: h0 = xn @ w_in^T + b_in (fp32 out)
    gemm(false, xnh, (long)HW * CIN, CIN, wh_in, 0, CIN, h0, nullptr,
         b_in, nullptr, 0.f, 1.f, HW, INNER, CIN);
    // 3. GN2(h0) -> hnh fp16
    gn2_k<<<NB * 32, 256>>>(sa_gng, sa_gnb);
    // 4a. q|k merged: qkh = hn @ [wq;wk]^T  [b, m, 1024]
    gemm(false, hnh, (long)HW * INNER, INNER, wh_saqk, 0, INNER,
         nullptr, qkh, nullptr, nullptr, 0.f, 1.f, HW, 1024, INNER);
    // 4b. v (transposed store, staged)
    gemm(true, hnh, (long)HW * INNER, INNER, wh_sav, 0, INNER,
         nullptr, vth, nullptr, nullptr, 0.f, 1.f, HW, INNER, INNER);
    // 5. sim = q @ k^T * c^-0.5 -> attnh fp16
    gemm(false, qkh, (long)HW * 1024, 1024, qkh + 512, (long)HW * 1024, 1024,
         nullptr, attnh, nullptr, nullptr, 0.f, inv_sqrt_c, HW, HW, INNER);
    // 6. softmax
    softmax_k<<<NB * HW, 256>>>();
    // 7. o = attn @ v -> oh fp16
    gemm(false, attnh, (long)HW * HW, HW, vth, (long)INNER * HW, HW,
         nullptr, oh, nullptr, nullptr, 0.f, 1.f, HW, INNER, HW);
    // 8. h1 = o @ wp^T + 2*h0 (fp32 + fp16 copies)
    gemm(false, oh, (long)HW * INNER, INNER, wh_sap, 0, INNER,
         h1, h1h, nullptr, h0, 2.f, 1.f, HW, INNER, INNER);
    // 9. CA projections: q fp16, fused k|v fp32
    gemm(false, h1h, (long)HW * INNER, INNER, wh_caq, 0, INNER,
         nullptr, qh, nullptr, nullptr, 0.f, 1.f, HW, INNER, INNER);
    gemm(false, ctx_h, (long)CTXN * CTXD, CTXD, wh_cakv, 0, CTXD,
         kvc, nullptr, nullptr, nullptr, 0.f, 1.f, CTXN, 1024, CTXD);
    // 10. fused cross-attention -> ofh fp16
    ca_attn_k<<<dim3(NB * 8, 4), 256>>>();
    // 11. h2 = o @ ca_wo^T + ca_bo + h1 -> h2h fp16
    gemm(false, ofh, (long)HW * INNER, INNER, wh_cao, 0, INNER,
         nullptr, h2h, ca_bo, h1, 1.f, 1.f, HW, INNER, INNER);
    // 12. out = h2 @ w_out^T + b_out + x (TOUT -> NCHW fp32, staged)
    gemm(true, h2h, (long)HW * INNER, INNER, wh_out, 0, INNER,
         out, nullptr, b_out, x, 1.f, 1.f, HW, CIN, INNER);
}